// round 1
// baseline (speedup 1.0000x reference)
#include <cuda_runtime.h>

#define TSEQ 4096
#define NB   4
#define BT   (TSEQ * NB)
#define CDIM 1024
#define HEAD 64

// Scratch for projected Q/K/V (allocation-free rule: __device__ globals)
__device__ float g_Q[BT * HEAD];
__device__ float g_K[BT * HEAD];
__device__ float g_V[BT * HEAD];

// 16B-chunk XOR swizzle for a [64][64] float tile: row r, 16B-chunk c4 (0..15).
// chunk' = c4 ^ ((r/4) & 7) keeps strided row accesses bank-conflict-free.
__device__ __forceinline__ int swz(int r, int c4) {
    return (r << 6) + ((c4 ^ ((r >> 2) & 7)) << 2);
}

// ---------------------------------------------------------------------------
// Projection: out[m][h] = sum_k x[m][k] * W[k][h], for (W,out) in
// {(Wk,g_K),(Wq,g_Q),(Wv,g_V)} selected by blockIdx.y. 64x64 output tile,
// BK=32, 4x4 micro-tile per thread.
// ---------------------------------------------------------------------------
__global__ __launch_bounds__(256) void proj_kernel(
    const float* __restrict__ x, const float* __restrict__ Wk,
    const float* __restrict__ Wq, const float* __restrict__ Wv)
{
    __shared__ float xs[64 * 32];
    __shared__ float ws[32 * 64];

    const float* W;
    float* out;
    if (blockIdx.y == 0)      { W = Wk; out = g_K; }
    else if (blockIdx.y == 1) { W = Wq; out = g_Q; }
    else                      { W = Wv; out = g_V; }

    const int m0  = blockIdx.x * 64;
    const int tid = threadIdx.x;
    const int ty  = tid >> 4;
    const int tx  = tid & 15;

    float acc[4][4];
    #pragma unroll
    for (int i = 0; i < 4; i++)
        #pragma unroll
        for (int c = 0; c < 4; c++) acc[i][c] = 0.f;

    for (int k0 = 0; k0 < CDIM; k0 += 32) {
        // x tile: 64 rows x 32 cols
        #pragma unroll
        for (int i = 0; i < 2; i++) {
            int idx = tid + i * 256;          // 512 float4 slots
            int r = idx >> 3;
            int c = (idx & 7) << 2;
            *(float4*)&xs[r * 32 + c] =
                *(const float4*)&x[(size_t)(m0 + r) * CDIM + k0 + c];
        }
        // W tile: 32 rows x 64 cols
        #pragma unroll
        for (int i = 0; i < 2; i++) {
            int idx = tid + i * 256;
            int r = idx >> 4;
            int c = (idx & 15) << 2;
            *(float4*)&ws[r * 64 + c] =
                *(const float4*)&W[(size_t)(k0 + r) * HEAD + c];
        }
        __syncthreads();

        #pragma unroll
        for (int kk4 = 0; kk4 < 8; kk4++) {
            float4 a[4], bb[4];
            #pragma unroll
            for (int i = 0; i < 4; i++)
                a[i] = *(float4*)&xs[(ty * 4 + i) * 32 + kk4 * 4];
            #pragma unroll
            for (int t = 0; t < 4; t++)
                bb[t] = *(float4*)&ws[(kk4 * 4 + t) * 64 + tx * 4];
            #pragma unroll
            for (int i = 0; i < 4; i++) {
                acc[i][0] += a[i].x*bb[0].x + a[i].y*bb[1].x + a[i].z*bb[2].x + a[i].w*bb[3].x;
                acc[i][1] += a[i].x*bb[0].y + a[i].y*bb[1].y + a[i].z*bb[2].y + a[i].w*bb[3].y;
                acc[i][2] += a[i].x*bb[0].z + a[i].y*bb[1].z + a[i].z*bb[2].z + a[i].w*bb[3].z;
                acc[i][3] += a[i].x*bb[0].w + a[i].y*bb[1].w + a[i].z*bb[2].w + a[i].w*bb[3].w;
            }
        }
        __syncthreads();
    }

    #pragma unroll
    for (int i = 0; i < 4; i++) {
        *(float4*)&out[(size_t)(m0 + ty * 4 + i) * HEAD + tx * 4] =
            make_float4(acc[i][0], acc[i][1], acc[i][2], acc[i][3]);
    }
}

// ---------------------------------------------------------------------------
// Flash attention, fp32, causal. One 64-query tile per CTA.
// S and P live in registers (4x4 per thread); P routed via SMEM (aliased with
// the K tile) for the P*V product. Online softmax per row.
// ---------------------------------------------------------------------------
__global__ __launch_bounds__(256) void attn_kernel(float* __restrict__ out)
{
    __shared__ float Qs[64 * 64];
    __shared__ float KPs[64 * 64];   // K tile, then reused as P tile
    __shared__ float Vs[64 * 64];

    const int b   = blockIdx.y;
    const int qb  = blockIdx.x;
    const int tid = threadIdx.x;
    const int ty  = tid >> 4;
    const int tx  = tid & 15;

    const float* Qg = g_Q + ((size_t)b * TSEQ + qb * 64) * HEAD;
    #pragma unroll
    for (int i = 0; i < 4; i++) {
        int idx = tid + i * 256;           // 1024 float4 slots
        int r = idx >> 4;
        int c4 = idx & 15;
        *(float4*)&Qs[swz(r, c4)] = *(const float4*)&Qg[r * HEAD + c4 * 4];
    }

    float m_i[4], l_i[4], o[4][4];
    #pragma unroll
    for (int i = 0; i < 4; i++) {
        m_i[i] = -1e30f;
        l_i[i] = 0.f;
        #pragma unroll
        for (int c = 0; c < 4; c++) o[i][c] = 0.f;
    }

    for (int j = 0; j <= qb; j++) {
        __syncthreads();   // previous-iter P/V reads done; Qs ready on iter 0
        const float* Kg = g_K + ((size_t)b * TSEQ + j * 64) * HEAD;
        const float* Vg = g_V + ((size_t)b * TSEQ + j * 64) * HEAD;
        #pragma unroll
        for (int i = 0; i < 4; i++) {
            int idx = tid + i * 256;
            int r = idx >> 4;
            int c4 = idx & 15;
            *(float4*)&KPs[swz(r, c4)] = *(const float4*)&Kg[r * HEAD + c4 * 4];
            *(float4*)&Vs[swz(r, c4)]  = *(const float4*)&Vg[r * HEAD + c4 * 4];
        }
        __syncthreads();

        // S = Q * K^T (4x4 per thread): rows ty*4+i, cols tx*4+t
        float s[4][4];
        #pragma unroll
        for (int i = 0; i < 4; i++)
            #pragma unroll
            for (int t = 0; t < 4; t++) s[i][t] = 0.f;

        #pragma unroll
        for (int h4 = 0; h4 < 16; h4++) {
            float4 q[4], k[4];
            #pragma unroll
            for (int i = 0; i < 4; i++)
                q[i] = *(float4*)&Qs[swz(ty * 4 + i, h4)];
            #pragma unroll
            for (int t = 0; t < 4; t++)
                k[t] = *(float4*)&KPs[swz(tx * 4 + t, h4)];
            #pragma unroll
            for (int i = 0; i < 4; i++) {
                #pragma unroll
                for (int t = 0; t < 4; t++) {
                    s[i][t] += q[i].x * k[t].x + q[i].y * k[t].y +
                               q[i].z * k[t].z + q[i].w * k[t].w;
                }
            }
        }
        __syncthreads();   // all K reads done before KPs becomes P

        // scale + causal mask + online softmax; write P into KPs
        #pragma unroll
        for (int i = 0; i < 4; i++) {
            const int rloc = ty * 4 + i;
            float mx = -1e30f;
            #pragma unroll
            for (int t = 0; t < 4; t++) {
                float v = s[i][t] * 0.125f;
                if (j == qb && (tx * 4 + t) > rloc) v = -1e9f;
                s[i][t] = v;
                mx = fmaxf(mx, v);
            }
            mx = fmaxf(mx, __shfl_xor_sync(0xffffffffu, mx, 1));
            mx = fmaxf(mx, __shfl_xor_sync(0xffffffffu, mx, 2));
            mx = fmaxf(mx, __shfl_xor_sync(0xffffffffu, mx, 4));
            mx = fmaxf(mx, __shfl_xor_sync(0xffffffffu, mx, 8));
            const float mnew = fmaxf(m_i[i], mx);
            const float corr = __expf(m_i[i] - mnew);
            m_i[i] = mnew;
            float rs = 0.f;
            #pragma unroll
            for (int t = 0; t < 4; t++) {
                float p = __expf(s[i][t] - mnew);
                s[i][t] = p;
                rs += p;
            }
            rs += __shfl_xor_sync(0xffffffffu, rs, 1);
            rs += __shfl_xor_sync(0xffffffffu, rs, 2);
            rs += __shfl_xor_sync(0xffffffffu, rs, 4);
            rs += __shfl_xor_sync(0xffffffffu, rs, 8);
            l_i[i] = l_i[i] * corr + rs;
            #pragma unroll
            for (int c = 0; c < 4; c++) o[i][c] *= corr;
            *(float4*)&KPs[swz(rloc, tx)] =
                make_float4(s[i][0], s[i][1], s[i][2], s[i][3]);
        }
        __syncthreads();

        // O += P * V  (cols tx*4..tx*4+3 of HEAD)
        #pragma unroll
        for (int s4 = 0; s4 < 16; s4++) {
            float4 p[4], v[4];
            #pragma unroll
            for (int i = 0; i < 4; i++)
                p[i] = *(float4*)&KPs[swz(ty * 4 + i, s4)];
            #pragma unroll
            for (int t = 0; t < 4; t++)
                v[t] = *(float4*)&Vs[swz(s4 * 4 + t, tx)];
            #pragma unroll
            for (int i = 0; i < 4; i++) {
                o[i][0] += p[i].x*v[0].x + p[i].y*v[1].x + p[i].z*v[2].x + p[i].w*v[3].x;
                o[i][1] += p[i].x*v[0].y + p[i].y*v[1].y + p[i].z*v[2].y + p[i].w*v[3].y;
                o[i][2] += p[i].x*v[0].z + p[i].y*v[1].z + p[i].z*v[2].z + p[i].w*v[3].z;
                o[i][3] += p[i].x*v[0].w + p[i].y*v[1].w + p[i].z*v[2].w + p[i].w*v[3].w;
            }
        }
    }

    const size_t orow = ((size_t)b * TSEQ + qb * 64 + ty * 4) * HEAD;
    #pragma unroll
    for (int i = 0; i < 4; i++) {
        const float inv = 1.0f / l_i[i];
        *(float4*)&out[orow + (size_t)i * HEAD + tx * 4] =
            make_float4(o[i][0] * inv, o[i][1] * inv,
                        o[i][2] * inv, o[i][3] * inv);
    }
}

extern "C" void kernel_launch(void* const* d_in, const int* in_sizes, int n_in,
                              void* d_out, int out_size)
{
    const float* x  = (const float*)d_in[0];
    const float* Wk = (const float*)d_in[1];
    const float* Wq = (const float*)d_in[2];
    const float* Wv = (const float*)d_in[3];
    float* out = (float*)d_out;

    proj_kernel<<<dim3(BT / 64, 3), 256>>>(x, Wk, Wq, Wv);
    attn_kernel<<<dim3(TSEQ / 64, NB), 256>>>(out);
}

// round 2
// speedup vs baseline: 1.2414x; 1.2414x over previous
#include <cuda_runtime.h>

#define TSEQ 4096
#define NB   4
#define BT   (TSEQ * NB)
#define CDIM 1024
#define HEAD 64
#define NT   (TSEQ / 64)   // 64 query tiles per batch

// Scratch for projected Q/K/V (allocation-free rule: __device__ globals)
__device__ float g_Q[BT * HEAD];
__device__ float g_K[BT * HEAD];
__device__ float g_V[BT * HEAD];

// 16B-chunk XOR swizzle for a [64][64] float tile: row r, 16B-chunk c4 (0..15).
__device__ __forceinline__ int swz(int r, int c4) {
    return (r << 6) + ((c4 ^ ((r >> 2) & 7)) << 2);
}

// ---------------------------------------------------------------------------
// Fused projection: one CTA computes a 64-row tile of K, Q and V at once.
// x tile loaded once per K-step; acc[4 rows][3 mats][4 cols] per thread.
// ---------------------------------------------------------------------------
__global__ __launch_bounds__(256, 2) void proj_kernel(
    const float* __restrict__ x, const float* __restrict__ Wk,
    const float* __restrict__ Wq, const float* __restrict__ Wv)
{
    __shared__ float xs[64 * 32];
    __shared__ float ws[3][32 * 64];

    const int m0  = blockIdx.x * 64;
    const int tid = threadIdx.x;
    const int ty  = tid >> 4;
    const int tx  = tid & 15;

    const float* Wm[3] = {Wk, Wq, Wv};

    float acc[4][3][4];
    #pragma unroll
    for (int i = 0; i < 4; i++)
        #pragma unroll
        for (int m = 0; m < 3; m++)
            #pragma unroll
            for (int c = 0; c < 4; c++) acc[i][m][c] = 0.f;

    for (int k0 = 0; k0 < CDIM; k0 += 32) {
        // x tile: 64 rows x 32 cols (512 float4 slots, 2 per thread)
        #pragma unroll
        for (int i = 0; i < 2; i++) {
            int idx = tid + i * 256;
            int r = idx >> 3;
            int c = (idx & 7) << 2;
            *(float4*)&xs[r * 32 + c] =
                *(const float4*)&x[(size_t)(m0 + r) * CDIM + k0 + c];
        }
        // W tiles: 3 x (32 rows x 64 cols), 2 float4 slots per thread each
        #pragma unroll
        for (int m = 0; m < 3; m++) {
            #pragma unroll
            for (int i = 0; i < 2; i++) {
                int idx = tid + i * 256;
                int r = idx >> 4;
                int c = (idx & 15) << 2;
                *(float4*)&ws[m][r * 64 + c] =
                    *(const float4*)&Wm[m][(size_t)(k0 + r) * HEAD + c];
            }
        }
        __syncthreads();

        #pragma unroll
        for (int kk4 = 0; kk4 < 8; kk4++) {
            float4 a[4];
            #pragma unroll
            for (int i = 0; i < 4; i++)
                a[i] = *(float4*)&xs[(ty * 4 + i) * 32 + kk4 * 4];
            #pragma unroll
            for (int m = 0; m < 3; m++) {
                float4 bb[4];
                #pragma unroll
                for (int t = 0; t < 4; t++)
                    bb[t] = *(float4*)&ws[m][(kk4 * 4 + t) * 64 + tx * 4];
                #pragma unroll
                for (int i = 0; i < 4; i++) {
                    acc[i][m][0] += a[i].x*bb[0].x + a[i].y*bb[1].x + a[i].z*bb[2].x + a[i].w*bb[3].x;
                    acc[i][m][1] += a[i].x*bb[0].y + a[i].y*bb[1].y + a[i].z*bb[2].y + a[i].w*bb[3].y;
                    acc[i][m][2] += a[i].x*bb[0].z + a[i].y*bb[1].z + a[i].z*bb[2].z + a[i].w*bb[3].z;
                    acc[i][m][3] += a[i].x*bb[0].w + a[i].y*bb[1].w + a[i].z*bb[2].w + a[i].w*bb[3].w;
                }
            }
        }
        __syncthreads();
    }

    float* Om[3] = {g_K, g_Q, g_V};
    #pragma unroll
    for (int m = 0; m < 3; m++) {
        #pragma unroll
        for (int i = 0; i < 4; i++) {
            *(float4*)&Om[m][(size_t)(m0 + ty * 4 + i) * HEAD + tx * 4] =
                make_float4(acc[i][m][0], acc[i][m][1], acc[i][m][2], acc[i][m][3]);
        }
    }
}

// ---------------------------------------------------------------------------
// Flash attention, fp32, causal. Balanced pairing: CTA x handles query tiles
// qb = x and qb = NT-1-x  ->  every CTA does exactly NT+1 KV-tile iterations.
// Grid (NT/2, NB) = 128 CTAs = one balanced wave. 2 CTAs/SM via reg cap.
// ---------------------------------------------------------------------------
__global__ __launch_bounds__(256, 2) void attn_kernel(float* __restrict__ out)
{
    __shared__ float Qs[64 * 64];
    __shared__ float KPs[64 * 64];   // K tile, then reused as P tile
    __shared__ float Vs[64 * 64];

    const int b   = blockIdx.y;
    const int tid = threadIdx.x;
    const int ty  = tid >> 4;
    const int tx  = tid & 15;

    #pragma unroll 1
    for (int pass = 0; pass < 2; pass++) {
        const int qb = pass ? (NT - 1 - blockIdx.x) : blockIdx.x;

        const float* Qg = g_Q + ((size_t)b * TSEQ + qb * 64) * HEAD;
        #pragma unroll
        for (int i = 0; i < 4; i++) {
            int idx = tid + i * 256;
            int r = idx >> 4;
            int c4 = idx & 15;
            *(float4*)&Qs[swz(r, c4)] = *(const float4*)&Qg[r * HEAD + c4 * 4];
        }

        float m_i[4], l_i[4], o[4][4];
        #pragma unroll
        for (int i = 0; i < 4; i++) {
            m_i[i] = -1e30f;
            l_i[i] = 0.f;
            #pragma unroll
            for (int c = 0; c < 4; c++) o[i][c] = 0.f;
        }

        #pragma unroll 1
        for (int j = 0; j <= qb; j++) {
            __syncthreads();   // prev-iter P/V reads done; Qs visible on iter 0
            const float* Kg = g_K + ((size_t)b * TSEQ + j * 64) * HEAD;
            const float* Vg = g_V + ((size_t)b * TSEQ + j * 64) * HEAD;
            #pragma unroll
            for (int i = 0; i < 4; i++) {
                int idx = tid + i * 256;
                int r = idx >> 4;
                int c4 = idx & 15;
                *(float4*)&KPs[swz(r, c4)] = *(const float4*)&Kg[r * HEAD + c4 * 4];
                *(float4*)&Vs[swz(r, c4)]  = *(const float4*)&Vg[r * HEAD + c4 * 4];
            }
            __syncthreads();

            // S = Q * K^T (4x4 per thread)
            float s[4][4];
            #pragma unroll
            for (int i = 0; i < 4; i++)
                #pragma unroll
                for (int t = 0; t < 4; t++) s[i][t] = 0.f;

            #pragma unroll
            for (int h4 = 0; h4 < 16; h4++) {
                float4 q[4], k[4];
                #pragma unroll
                for (int i = 0; i < 4; i++)
                    q[i] = *(float4*)&Qs[swz(ty * 4 + i, h4)];
                #pragma unroll
                for (int t = 0; t < 4; t++)
                    k[t] = *(float4*)&KPs[swz(tx * 4 + t, h4)];
                #pragma unroll
                for (int i = 0; i < 4; i++) {
                    #pragma unroll
                    for (int t = 0; t < 4; t++) {
                        s[i][t] += q[i].x * k[t].x + q[i].y * k[t].y +
                                   q[i].z * k[t].z + q[i].w * k[t].w;
                    }
                }
            }
            __syncthreads();   // all K reads done before KPs becomes P

            // scale + causal mask + online softmax; write P into KPs
            #pragma unroll
            for (int i = 0; i < 4; i++) {
                const int rloc = ty * 4 + i;
                float mx = -1e30f;
                #pragma unroll
                for (int t = 0; t < 4; t++) {
                    float v = s[i][t] * 0.125f;
                    if (j == qb && (tx * 4 + t) > rloc) v = -1e9f;
                    s[i][t] = v;
                    mx = fmaxf(mx, v);
                }
                mx = fmaxf(mx, __shfl_xor_sync(0xffffffffu, mx, 1));
                mx = fmaxf(mx, __shfl_xor_sync(0xffffffffu, mx, 2));
                mx = fmaxf(mx, __shfl_xor_sync(0xffffffffu, mx, 4));
                mx = fmaxf(mx, __shfl_xor_sync(0xffffffffu, mx, 8));
                const float mnew = fmaxf(m_i[i], mx);
                const float corr = __expf(m_i[i] - mnew);
                m_i[i] = mnew;
                float rs = 0.f;
                #pragma unroll
                for (int t = 0; t < 4; t++) {
                    float p = __expf(s[i][t] - mnew);
                    s[i][t] = p;
                    rs += p;
                }
                rs += __shfl_xor_sync(0xffffffffu, rs, 1);
                rs += __shfl_xor_sync(0xffffffffu, rs, 2);
                rs += __shfl_xor_sync(0xffffffffu, rs, 4);
                rs += __shfl_xor_sync(0xffffffffu, rs, 8);
                l_i[i] = l_i[i] * corr + rs;
                #pragma unroll
                for (int c = 0; c < 4; c++) o[i][c] *= corr;
                *(float4*)&KPs[swz(rloc, tx)] =
                    make_float4(s[i][0], s[i][1], s[i][2], s[i][3]);
            }
            __syncthreads();

            // O += P * V
            #pragma unroll
            for (int s4 = 0; s4 < 16; s4++) {
                float4 p[4], v[4];
                #pragma unroll
                for (int i = 0; i < 4; i++)
                    p[i] = *(float4*)&KPs[swz(ty * 4 + i, s4)];
                #pragma unroll
                for (int t = 0; t < 4; t++)
                    v[t] = *(float4*)&Vs[swz(s4 * 4 + t, tx)];
                #pragma unroll
                for (int i = 0; i < 4; i++) {
                    o[i][0] += p[i].x*v[0].x + p[i].y*v[1].x + p[i].z*v[2].x + p[i].w*v[3].x;
                    o[i][1] += p[i].x*v[0].y + p[i].y*v[1].y + p[i].z*v[2].y + p[i].w*v[3].y;
                    o[i][2] += p[i].x*v[0].z + p[i].y*v[1].z + p[i].z*v[2].z + p[i].w*v[3].z;
                    o[i][3] += p[i].x*v[0].w + p[i].y*v[1].w + p[i].z*v[2].w + p[i].w*v[3].w;
                }
            }
        }

        const size_t orow = ((size_t)b * TSEQ + qb * 64 + ty * 4) * HEAD;
        #pragma unroll
        for (int i = 0; i < 4; i++) {
            const float inv = 1.0f / l_i[i];
            *(float4*)&out[orow + (size_t)i * HEAD + tx * 4] =
                make_float4(o[i][0] * inv, o[i][1] * inv,
                            o[i][2] * inv, o[i][3] * inv);
        }
        // No extra sync needed: the j-loop's leading __syncthreads() of the
        // next pass protects KPs/Vs, and Qs overwrite is ordered by the final
        // iteration's post-S barrier (all warps past it before any P/V read).
    }
}

extern "C" void kernel_launch(void* const* d_in, const int* in_sizes, int n_in,
                              void* d_out, int out_size)
{
    const float* x  = (const float*)d_in[0];
    const float* Wk = (const float*)d_in[1];
    const float* Wq = (const float*)d_in[2];
    const float* Wv = (const float*)d_in[3];
    float* out = (float*)d_out;

    proj_kernel<<<dim3(BT / 64), 256>>>(x, Wk, Wq, Wv);
    attn_kernel<<<dim3(NT / 2, NB), 256>>>(out);
}

// round 5
// speedup vs baseline: 2.0236x; 1.6301x over previous
#include <cuda_runtime.h>
#include <cstdint>

#define TSEQ 4096
#define NB   4
#define BT   (TSEQ * NB)
#define CDIM 1024
#define HEAD 64
#define QT   128               // queries per attn CTA
#define NQT  (TSEQ / QT)       // 32 query tiles per batch

// Scratch (allocation-free rule: __device__ globals)
__device__ float g_Q[BT * HEAD];
__device__ float g_K[BT * HEAD];
__device__ float g_V[BT * HEAD];

__device__ __forceinline__ float tf32_rna(float x) {
    uint32_t u;
    asm("cvt.rna.tf32.f32 %0, %1;" : "=r"(u) : "f"(x));
    return __uint_as_float(u);
}

// m16n8k8 tf32 mma: A row-major (4 regs), B col-major (2 regs), C fp32 (4 regs)
__device__ __forceinline__ void mma_tf32(float* c, const uint32_t* a,
                                         uint32_t b0, uint32_t b1) {
    asm volatile(
        "mma.sync.aligned.m16n8k8.row.col.f32.tf32.tf32.f32 "
        "{%0,%1,%2,%3}, {%4,%5,%6,%7}, {%8,%9}, {%0,%1,%2,%3};"
        : "+f"(c[0]), "+f"(c[1]), "+f"(c[2]), "+f"(c[3])
        : "r"(a[0]), "r"(a[1]), "r"(a[2]), "r"(a[3]), "r"(b0), "r"(b1));
}

// ===========================================================================
// Fused projection (fp32 FFMA, exact): K,Q,V = x @ W*. M-tile 128 -> grid 128
// CTAs = one full wave. Outputs rounded once to tf32 (RNA) for the attn mmas.
// ===========================================================================
__global__ __launch_bounds__(256, 1) void proj_kernel(
    const float* __restrict__ x, const float* __restrict__ Wk,
    const float* __restrict__ Wq, const float* __restrict__ Wv)
{
    __shared__ float xs[128 * 32];
    __shared__ float ws[3][32 * 64];

    const int m0  = blockIdx.x * 128;
    const int tid = threadIdx.x;
    const int ty  = tid >> 4;    // 0..15
    const int tx  = tid & 15;    // 0..15

    const float* Wm[3] = {Wk, Wq, Wv};

    float acc[2][4][3][4];       // [row-half][row i][mat][col]
    #pragma unroll
    for (int h = 0; h < 2; h++)
        #pragma unroll
        for (int i = 0; i < 4; i++)
            #pragma unroll
            for (int m = 0; m < 3; m++)
                #pragma unroll
                for (int c = 0; c < 4; c++) acc[h][i][m][c] = 0.f;

    for (int k0 = 0; k0 < CDIM; k0 += 32) {
        // x tile: 128 rows x 32 cols = 1024 float4, 4 per thread
        #pragma unroll
        for (int i = 0; i < 4; i++) {
            int idx = tid + i * 256;
            int r = idx >> 3;
            int c = (idx & 7) << 2;
            *(float4*)&xs[r * 32 + c] =
                *(const float4*)&x[(size_t)(m0 + r) * CDIM + k0 + c];
        }
        // W tiles: 3 x (32 x 64), 2 float4 per thread each
        #pragma unroll
        for (int m = 0; m < 3; m++) {
            #pragma unroll
            for (int i = 0; i < 2; i++) {
                int idx = tid + i * 256;
                int r = idx >> 4;
                int c = (idx & 15) << 2;
                *(float4*)&ws[m][r * 64 + c] =
                    *(const float4*)&Wm[m][(size_t)(k0 + r) * HEAD + c];
            }
        }
        __syncthreads();

        #pragma unroll
        for (int kk4 = 0; kk4 < 8; kk4++) {
            float4 a[2][4];
            #pragma unroll
            for (int h = 0; h < 2; h++)
                #pragma unroll
                for (int i = 0; i < 4; i++)
                    a[h][i] = *(float4*)&xs[(h * 64 + ty * 4 + i) * 32 + kk4 * 4];
            #pragma unroll
            for (int m = 0; m < 3; m++) {
                float4 bb[4];
                #pragma unroll
                for (int t = 0; t < 4; t++)
                    bb[t] = *(float4*)&ws[m][(kk4 * 4 + t) * 64 + tx * 4];
                #pragma unroll
                for (int h = 0; h < 2; h++) {
                    #pragma unroll
                    for (int i = 0; i < 4; i++) {
                        acc[h][i][m][0] += a[h][i].x*bb[0].x + a[h][i].y*bb[1].x + a[h][i].z*bb[2].x + a[h][i].w*bb[3].x;
                        acc[h][i][m][1] += a[h][i].x*bb[0].y + a[h][i].y*bb[1].y + a[h][i].z*bb[2].y + a[h][i].w*bb[3].y;
                        acc[h][i][m][2] += a[h][i].x*bb[0].z + a[h][i].y*bb[1].z + a[h][i].z*bb[2].z + a[h][i].w*bb[3].z;
                        acc[h][i][m][3] += a[h][i].x*bb[0].w + a[h][i].y*bb[1].w + a[h][i].z*bb[2].w + a[h][i].w*bb[3].w;
                    }
                }
            }
        }
        __syncthreads();
    }

    float* Om[3] = {g_K, g_Q, g_V};
    #pragma unroll
    for (int m = 0; m < 3; m++) {
        #pragma unroll
        for (int h = 0; h < 2; h++) {
            #pragma unroll
            for (int i = 0; i < 4; i++) {
                *(float4*)&Om[m][(size_t)(m0 + h * 64 + ty * 4 + i) * HEAD + tx * 4] =
                    make_float4(tf32_rna(acc[h][i][m][0]), tf32_rna(acc[h][i][m][1]),
                                tf32_rna(acc[h][i][m][2]), tf32_rna(acc[h][i][m][3]));
            }
        }
    }
}

// ===========================================================================
// Flash attention with mma.sync tf32. QT=128 queries/CTA, KV tiles of 128.
// 8 warps x 16 query rows. Q A-frags in registers; P via smem round-trip.
// ===========================================================================
#define LDK 68                  // K tile pitch: 64 cols + 4 pad
#define LDV 72                  // V tile pitch: 64 cols + 8 pad
#define LDP 136                 // P tile pitch: 128 cols + 8 pad
#define KS_OFF 0
#define VS_OFF (128 * LDK)
#define PS_OFF (VS_OFF + 128 * LDV)
#define SMEM_FLOATS (PS_OFF + 128 * LDP)

__global__ __launch_bounds__(256, 1) void attn_kernel(float* __restrict__ out)
{
    extern __shared__ float sm[];
    float* Ks = sm + KS_OFF;
    float* Vs = sm + VS_OFF;
    float* Ps = sm + PS_OFF;

    const int tid  = threadIdx.x;
    const int w    = tid >> 5;
    const int lane = tid & 31;
    const int g    = lane >> 2;      // group 0..7
    const int tig  = lane & 3;       // 0..3
    const int wrow = w * 16;         // warp's query-row base (local)
    const int b    = blockIdx.y;
    const int qb   = blockIdx.x;
    const int q0   = qb * QT;

    // Preload Q A-frags (scaled by 0.125 — exact power of 2, stays tf32)
    uint32_t aq[8][4];
    {
        const float* Qb = g_Q + ((size_t)(b * TSEQ + q0 + wrow)) * HEAD;
        #pragma unroll
        for (int k = 0; k < 8; k++) {
            aq[k][0] = __float_as_uint(0.125f * Qb[(size_t)g * HEAD + 8 * k + tig]);
            aq[k][1] = __float_as_uint(0.125f * Qb[(size_t)(g + 8) * HEAD + 8 * k + tig]);
            aq[k][2] = __float_as_uint(0.125f * Qb[(size_t)g * HEAD + 8 * k + tig + 4]);
            aq[k][3] = __float_as_uint(0.125f * Qb[(size_t)(g + 8) * HEAD + 8 * k + tig + 4]);
        }
    }

    float O[8][4];
    #pragma unroll
    for (int n = 0; n < 8; n++)
        #pragma unroll
        for (int c = 0; c < 4; c++) O[n][c] = 0.f;
    float m0r = -1e30f, m1r = -1e30f, l0 = 0.f, l1 = 0.f;

    #pragma unroll 1
    for (int j = 0; j <= qb; j++) {
        const int kv0 = j * QT;
        __syncthreads();   // prev-iter Ks/Vs readers done
        {
            const float* Kg = g_K + ((size_t)(b * TSEQ + kv0)) * HEAD;
            const float* Vg = g_V + ((size_t)(b * TSEQ + kv0)) * HEAD;
            #pragma unroll
            for (int i = 0; i < 8; i++) {
                int idx = tid + i * 256;
                int r = idx >> 4, c4 = idx & 15;
                *(float4*)&Ks[r * LDK + c4 * 4] =
                    *(const float4*)&Kg[(size_t)r * HEAD + c4 * 4];
                *(float4*)&Vs[r * LDV + c4 * 4] =
                    *(const float4*)&Vg[(size_t)r * HEAD + c4 * 4];
            }
        }
        __syncthreads();

        // ---- S = (0.125 Q) K^T : 16 n-tiles x 8 k-steps ----
        float s[16][4];
        #pragma unroll
        for (int nt = 0; nt < 16; nt++)
            #pragma unroll
            for (int c = 0; c < 4; c++) s[nt][c] = 0.f;

        #pragma unroll
        for (int k = 0; k < 8; k++) {
            #pragma unroll
            for (int nt = 0; nt < 16; nt++) {
                uint32_t b0 = *(const uint32_t*)&Ks[(8 * nt + g) * LDK + 8 * k + tig];
                uint32_t b1 = *(const uint32_t*)&Ks[(8 * nt + g) * LDK + 8 * k + tig + 4];
                mma_tf32(s[nt], aq[k], b0, b1);
            }
        }

        // ---- mask (diag tile) + row max ----
        const int r0 = wrow + g;       // local rows r0, r0+8
        float mx0 = -1e30f, mx1 = -1e30f;
        const bool diag = (j == qb);
        #pragma unroll
        for (int nt = 0; nt < 16; nt++) {
            const int c0 = 8 * nt + 2 * tig;
            if (diag) {
                if (c0     > r0)     s[nt][0] = -1e30f;
                if (c0 + 1 > r0)     s[nt][1] = -1e30f;
                if (c0     > r0 + 8) s[nt][2] = -1e30f;
                if (c0 + 1 > r0 + 8) s[nt][3] = -1e30f;
            }
            mx0 = fmaxf(mx0, fmaxf(s[nt][0], s[nt][1]));
            mx1 = fmaxf(mx1, fmaxf(s[nt][2], s[nt][3]));
        }
        mx0 = fmaxf(mx0, __shfl_xor_sync(0xffffffffu, mx0, 1));
        mx0 = fmaxf(mx0, __shfl_xor_sync(0xffffffffu, mx0, 2));
        mx1 = fmaxf(mx1, __shfl_xor_sync(0xffffffffu, mx1, 1));
        mx1 = fmaxf(mx1, __shfl_xor_sync(0xffffffffu, mx1, 2));

        const float mn0 = fmaxf(m0r, mx0);
        const float mn1 = fmaxf(m1r, mx1);
        const float corr0 = __expf(m0r - mn0);
        const float corr1 = __expf(m1r - mn1);
        m0r = mn0; m1r = mn1;

        // ---- exp (rna-rounded to tf32), P -> smem, row sums ----
        float sum0 = 0.f, sum1 = 0.f;
        #pragma unroll
        for (int nt = 0; nt < 16; nt++) {
            float p0 = tf32_rna(__expf(s[nt][0] - mn0));
            float p1 = tf32_rna(__expf(s[nt][1] - mn0));
            float p2 = tf32_rna(__expf(s[nt][2] - mn1));
            float p3 = tf32_rna(__expf(s[nt][3] - mn1));
            sum0 += p0 + p1;
            sum1 += p2 + p3;
            *(float2*)&Ps[(r0)     * LDP + 8 * nt + 2 * tig] = make_float2(p0, p1);
            *(float2*)&Ps[(r0 + 8) * LDP + 8 * nt + 2 * tig] = make_float2(p2, p3);
        }
        sum0 += __shfl_xor_sync(0xffffffffu, sum0, 1);
        sum0 += __shfl_xor_sync(0xffffffffu, sum0, 2);
        sum1 += __shfl_xor_sync(0xffffffffu, sum1, 1);
        sum1 += __shfl_xor_sync(0xffffffffu, sum1, 2);
        l0 = l0 * corr0 + sum0;
        l1 = l1 * corr1 + sum1;

        // rescale O
        #pragma unroll
        for (int n = 0; n < 8; n++) {
            O[n][0] *= corr0; O[n][1] *= corr0;
            O[n][2] *= corr1; O[n][3] *= corr1;
        }
        __syncwarp();   // own-warp P rows: sts -> lds ordering

        // ---- O += P V : 16 k-steps x 8 n-tiles ----
        #pragma unroll
        for (int k2 = 0; k2 < 16; k2++) {
            uint32_t a[4];
            a[0] = *(const uint32_t*)&Ps[(r0)     * LDP + 8 * k2 + tig];
            a[1] = *(const uint32_t*)&Ps[(r0 + 8) * LDP + 8 * k2 + tig];
            a[2] = *(const uint32_t*)&Ps[(r0)     * LDP + 8 * k2 + tig + 4];
            a[3] = *(const uint32_t*)&Ps[(r0 + 8) * LDP + 8 * k2 + tig + 4];
            #pragma unroll
            for (int nt = 0; nt < 8; nt++) {
                uint32_t b0 = *(const uint32_t*)&Vs[(8 * k2 + tig)     * LDV + 8 * nt + g];
                uint32_t b1 = *(const uint32_t*)&Vs[(8 * k2 + tig + 4) * LDV + 8 * nt + g];
                mma_tf32(O[nt], a, b0, b1);
            }
        }
    }

    // ---- epilogue ----
    const float inv0 = 1.0f / l0;
    const float inv1 = 1.0f / l1;
    float* o0 = out + ((size_t)(b * TSEQ + q0 + wrow + g)) * HEAD;
    float* o1 = out + ((size_t)(b * TSEQ + q0 + wrow + g + 8)) * HEAD;
    #pragma unroll
    for (int nt = 0; nt < 8; nt++) {
        *(float2*)&o0[8 * nt + 2 * tig] = make_float2(O[nt][0] * inv0, O[nt][1] * inv0);
        *(float2*)&o1[8 * nt + 2 * tig] = make_float2(O[nt][2] * inv1, O[nt][3] * inv1);
    }
}

extern "C" void kernel_launch(void* const* d_in, const int* in_sizes, int n_in,
                              void* d_out, int out_size)
{
    const float* x  = (const float*)d_in[0];
    const float* Wk = (const float*)d_in[1];
    const float* Wq = (const float*)d_in[2];
    const float* Wv = (const float*)d_in[3];
    float* out = (float*)d_out;

    cudaFuncSetAttribute(attn_kernel,
                         cudaFuncAttributeMaxDynamicSharedMemorySize,
                         SMEM_FLOATS * (int)sizeof(float));

    proj_kernel<<<dim3(BT / 128), 256>>>(x, Wk, Wq, Wv);
    attn_kernel<<<dim3(NQT, NB), 256, SMEM_FLOATS * sizeof(float)>>>(out);
}

// round 8
// speedup vs baseline: 2.5668x; 1.2685x over previous
#include <cuda_runtime.h>
#include <cstdint>

#define TSEQ 4096
#define NB   4
#define BT   (TSEQ * NB)
#define CDIM 1024
#define HEAD 64
#define QT   128               // queries per attn CTA
#define NQT  (TSEQ / QT)       // 32 query tiles per batch

// Scratch (allocation-free rule: __device__ globals)
__device__ float g_Q[BT * HEAD];
__device__ float g_K[BT * HEAD];
__device__ float g_V[BT * HEAD];

__device__ __forceinline__ float tf32_rna(float x) {
    uint32_t u;
    asm("cvt.rna.tf32.f32 %0, %1;" : "=r"(u) : "f"(x));
    return __uint_as_float(u);
}

// m16n8k8 tf32 mma: A row-major (4 regs), B col-major (2 regs), C fp32 (4 regs)
__device__ __forceinline__ void mma_tf32(float* c, const uint32_t* a,
                                         uint32_t b0, uint32_t b1) {
    asm volatile(
        "mma.sync.aligned.m16n8k8.row.col.f32.tf32.tf32.f32 "
        "{%0,%1,%2,%3}, {%4,%5,%6,%7}, {%8,%9}, {%0,%1,%2,%3};"
        : "+f"(c[0]), "+f"(c[1]), "+f"(c[2]), "+f"(c[3])
        : "r"(a[0]), "r"(a[1]), "r"(a[2]), "r"(a[3]), "r"(b0), "r"(b1));
}

__device__ __forceinline__ void cp16(uint32_t s, const void* g) {
    asm volatile("cp.async.cg.shared.global [%0], [%1], 16;" :: "r"(s), "l"(g));
}
#define CP_COMMIT() asm volatile("cp.async.commit_group;" ::: "memory")
#define CP_WAIT0()  asm volatile("cp.async.wait_group 0;" ::: "memory")

__device__ __forceinline__ uint32_t smem_u32(const void* p) {
    uint32_t a;
    asm("{ .reg .u64 t; cvta.to.shared.u64 t, %1; cvt.u32.u64 %0, t; }"
        : "=r"(a) : "l"(p));
    return a;
}

// ===========================================================================
// Projection via 3xTF32 mma (error-compensated; ~fp32 accuracy).
// One CTA: 128 rows x 192 cols (K|Q|V). 8 warps as 4x2; warp tile 32x96.
// BK=32. x,W split into tf32 hi+lo; acc += xh*wh + xl*wh + xh*wl.
// ===========================================================================
#define XPITCH 36
#define WPITCH 200
#define XH_OFF 0
#define XL_OFF (128 * XPITCH)
#define WH_OFF (2 * 128 * XPITCH)
#define WL_OFF (WH_OFF + 32 * WPITCH)
#define PROJ_SMEM_FLOATS (WL_OFF + 32 * WPITCH)

__global__ __launch_bounds__(256, 1) void proj_kernel(
    const float* __restrict__ x, const float* __restrict__ Wk,
    const float* __restrict__ Wq, const float* __restrict__ Wv)
{
    extern __shared__ float psm[];
    float* xh = psm + XH_OFF;
    float* xl = psm + XL_OFF;
    float* wh = psm + WH_OFF;
    float* wl = psm + WL_OFF;

    const int tid  = threadIdx.x;
    const int w    = tid >> 5;
    const int lane = tid & 31;
    const int g    = lane >> 2;
    const int tig  = lane & 3;
    const int wr   = w >> 1;      // 0..3
    const int wc   = w & 1;       // 0..1
    const int m0   = blockIdx.x * 128;

    const float* Wm[3] = {Wk, Wq, Wv};

    float acc[2][12][4];
    #pragma unroll
    for (int mt = 0; mt < 2; mt++)
        #pragma unroll
        for (int n = 0; n < 12; n++)
            #pragma unroll
            for (int c = 0; c < 4; c++) acc[mt][n][c] = 0.f;

    for (int k0 = 0; k0 < CDIM; k0 += 32) {
        // x tile 128x32 -> hi/lo
        #pragma unroll
        for (int i = 0; i < 4; i++) {
            int idx = tid + i * 256;             // 1024 float4 slots
            int r = idx >> 3, c4 = idx & 7;
            float4 v = *(const float4*)&x[(size_t)(m0 + r) * CDIM + k0 + c4 * 4];
            float h0 = tf32_rna(v.x), h1 = tf32_rna(v.y),
                  h2 = tf32_rna(v.z), h3 = tf32_rna(v.w);
            float* ph = &xh[r * XPITCH + c4 * 4];
            float* pl = &xl[r * XPITCH + c4 * 4];
            ph[0] = h0; ph[1] = h1; ph[2] = h2; ph[3] = h3;
            pl[0] = tf32_rna(v.x - h0); pl[1] = tf32_rna(v.y - h1);
            pl[2] = tf32_rna(v.z - h2); pl[3] = tf32_rna(v.w - h3);
        }
        // W tiles 3 x (32x64) -> hi/lo at col offset m*64
        #pragma unroll
        for (int m = 0; m < 3; m++) {
            #pragma unroll
            for (int i = 0; i < 2; i++) {
                int idx = tid + i * 256;         // 512 float4 slots
                int r = idx >> 4, c4 = idx & 15;
                float4 v = *(const float4*)&Wm[m][(size_t)(k0 + r) * HEAD + c4 * 4];
                float h0 = tf32_rna(v.x), h1 = tf32_rna(v.y),
                      h2 = tf32_rna(v.z), h3 = tf32_rna(v.w);
                float* ph = &wh[r * WPITCH + m * 64 + c4 * 4];
                float* pl = &wl[r * WPITCH + m * 64 + c4 * 4];
                ph[0] = h0; ph[1] = h1; ph[2] = h2; ph[3] = h3;
                pl[0] = tf32_rna(v.x - h0); pl[1] = tf32_rna(v.y - h1);
                pl[2] = tf32_rna(v.z - h2); pl[3] = tf32_rna(v.w - h3);
            }
        }
        __syncthreads();

        #pragma unroll
        for (int ks = 0; ks < 4; ks++) {
            uint32_t ah[2][4], al[2][4];
            #pragma unroll
            for (int mt = 0; mt < 2; mt++) {
                const int rb = 32 * wr + 16 * mt;
                ah[mt][0] = __float_as_uint(xh[(rb + g)     * XPITCH + 8 * ks + tig]);
                ah[mt][1] = __float_as_uint(xh[(rb + g + 8) * XPITCH + 8 * ks + tig]);
                ah[mt][2] = __float_as_uint(xh[(rb + g)     * XPITCH + 8 * ks + tig + 4]);
                ah[mt][3] = __float_as_uint(xh[(rb + g + 8) * XPITCH + 8 * ks + tig + 4]);
                al[mt][0] = __float_as_uint(xl[(rb + g)     * XPITCH + 8 * ks + tig]);
                al[mt][1] = __float_as_uint(xl[(rb + g + 8) * XPITCH + 8 * ks + tig]);
                al[mt][2] = __float_as_uint(xl[(rb + g)     * XPITCH + 8 * ks + tig + 4]);
                al[mt][3] = __float_as_uint(xl[(rb + g + 8) * XPITCH + 8 * ks + tig + 4]);
            }
            #pragma unroll
            for (int n = 0; n < 12; n++) {
                const int col = 96 * wc + 8 * n + g;
                uint32_t bh0 = __float_as_uint(wh[(8 * ks + tig)     * WPITCH + col]);
                uint32_t bh1 = __float_as_uint(wh[(8 * ks + tig + 4) * WPITCH + col]);
                uint32_t bl0 = __float_as_uint(wl[(8 * ks + tig)     * WPITCH + col]);
                uint32_t bl1 = __float_as_uint(wl[(8 * ks + tig + 4) * WPITCH + col]);
                #pragma unroll
                for (int mt = 0; mt < 2; mt++) {
                    mma_tf32(acc[mt][n], al[mt], bh0, bh1);
                    mma_tf32(acc[mt][n], ah[mt], bl0, bl1);
                    mma_tf32(acc[mt][n], ah[mt], bh0, bh1);
                }
            }
        }
        __syncthreads();
    }

    // epilogue: rna-round once, store to g_K/g_Q/g_V
    float* Om[3] = {g_K, g_Q, g_V};
    #pragma unroll
    for (int n = 0; n < 12; n++) {
        const int colg = 96 * wc + 8 * n + 2 * tig;
        float* dst = Om[colg >> 6];
        const int cin = colg & 63;
        #pragma unroll
        for (int mt = 0; mt < 2; mt++) {
            const int row = m0 + 32 * wr + 16 * mt + g;
            *(float2*)&dst[(size_t)row * HEAD + cin] =
                make_float2(tf32_rna(acc[mt][n][0]), tf32_rna(acc[mt][n][1]));
            *(float2*)&dst[(size_t)(row + 8) * HEAD + cin] =
                make_float2(tf32_rna(acc[mt][n][2]), tf32_rna(acc[mt][n][3]));
        }
    }
}

// ===========================================================================
// Flash attention with mma.sync tf32 + cp.async double-buffered K/V tiles.
// QT=128 queries/CTA, KV tiles of 128. 8 warps x 16 query rows.
// ===========================================================================
#define LDK 68                  // K tile pitch: 64 cols + 4 pad
#define LDV 72                  // V tile pitch: 64 cols + 8 pad
#define LDP 136                 // P tile pitch: 128 cols + 8 pad
#define KS_SZ (128 * LDK)
#define VS_SZ (128 * LDV)
#define KS_OFF 0
#define VS_OFF (2 * KS_SZ)
#define PS_OFF (VS_OFF + 2 * VS_SZ)
#define ATTN_SMEM_FLOATS (PS_OFF + 128 * LDP)

__global__ __launch_bounds__(256, 1) void attn_kernel(float* __restrict__ out)
{
    extern __shared__ float sm[];
    float* Ps = sm + PS_OFF;
    const uint32_t smb = smem_u32(sm);

    const int tid  = threadIdx.x;
    const int w    = tid >> 5;
    const int lane = tid & 31;
    const int g    = lane >> 2;      // group 0..7
    const int tig  = lane & 3;       // 0..3
    const int wrow = w * 16;         // warp's query-row base (local)
    const int b    = blockIdx.y;
    const int qb   = blockIdx.x;
    const int q0   = qb * QT;

    // per-thread cp.async slot: idx in [0,2048) float4 slots, 8 per thread
    const int cprow = tid >> 4;          // with i*16 stride below
    const int cpc4  = tid & 15;

    const float* Kg0 = g_K + ((size_t)(b * TSEQ)) * HEAD;
    const float* Vg0 = g_V + ((size_t)(b * TSEQ)) * HEAD;

    // prefetch tile 0 into buffer 0
    {
        const float* Kg = Kg0;
        const float* Vg = Vg0;
        #pragma unroll
        for (int i = 0; i < 8; i++) {
            int r = cprow + i * 16;
            cp16(smb + (uint32_t)(KS_OFF + r * LDK + cpc4 * 4) * 4,
                 &Kg[(size_t)r * HEAD + cpc4 * 4]);
            cp16(smb + (uint32_t)(VS_OFF + r * LDV + cpc4 * 4) * 4,
                 &Vg[(size_t)r * HEAD + cpc4 * 4]);
        }
        CP_COMMIT();
    }

    // Preload Q A-frags (scaled by 0.125 — exact power of 2, stays tf32)
    uint32_t aq[8][4];
    {
        const float* Qb = g_Q + ((size_t)(b * TSEQ + q0 + wrow)) * HEAD;
        #pragma unroll
        for (int k = 0; k < 8; k++) {
            aq[k][0] = __float_as_uint(0.125f * Qb[(size_t)g * HEAD + 8 * k + tig]);
            aq[k][1] = __float_as_uint(0.125f * Qb[(size_t)(g + 8) * HEAD + 8 * k + tig]);
            aq[k][2] = __float_as_uint(0.125f * Qb[(size_t)g * HEAD + 8 * k + tig + 4]);
            aq[k][3] = __float_as_uint(0.125f * Qb[(size_t)(g + 8) * HEAD + 8 * k + tig + 4]);
        }
    }

    float O[8][4];
    #pragma unroll
    for (int n = 0; n < 8; n++)
        #pragma unroll
        for (int c = 0; c < 4; c++) O[n][c] = 0.f;
    float m0r = -1e30f, m1r = -1e30f, l0 = 0.f, l1 = 0.f;
    int buf = 0;

    #pragma unroll 1
    for (int j = 0; j <= qb; j++) {
        CP_WAIT0();
        __syncthreads();          // tile j visible to all; prev compute done

        if (j < qb) {             // prefetch tile j+1 into other buffer
            const int nb = buf ^ 1;
            const float* Kg = Kg0 + (size_t)(j + 1) * QT * HEAD;
            const float* Vg = Vg0 + (size_t)(j + 1) * QT * HEAD;
            #pragma unroll
            for (int i = 0; i < 8; i++) {
                int r = cprow + i * 16;
                cp16(smb + (uint32_t)(KS_OFF + nb * KS_SZ + r * LDK + cpc4 * 4) * 4,
                     &Kg[(size_t)r * HEAD + cpc4 * 4]);
                cp16(smb + (uint32_t)(VS_OFF + nb * VS_SZ + r * LDV + cpc4 * 4) * 4,
                     &Vg[(size_t)r * HEAD + cpc4 * 4]);
            }
            CP_COMMIT();
        }

        const float* Ks = sm + KS_OFF + buf * KS_SZ;
        const float* Vs = sm + VS_OFF + buf * VS_SZ;

        // ---- S = (0.125 Q) K^T : 16 n-tiles x 8 k-steps ----
        float s[16][4];
        #pragma unroll
        for (int nt = 0; nt < 16; nt++)
            #pragma unroll
            for (int c = 0; c < 4; c++) s[nt][c] = 0.f;

        #pragma unroll
        for (int k = 0; k < 8; k++) {
            #pragma unroll
            for (int nt = 0; nt < 16; nt++) {
                uint32_t b0 = *(const uint32_t*)&Ks[(8 * nt + g) * LDK + 8 * k + tig];
                uint32_t b1 = *(const uint32_t*)&Ks[(8 * nt + g) * LDK + 8 * k + tig + 4];
                mma_tf32(s[nt], aq[k], b0, b1);
            }
        }

        // ---- mask (diag tile) + row max ----
        const int r0 = wrow + g;       // local rows r0, r0+8
        float mx0 = -1e30f, mx1 = -1e30f;
        const bool diag = (j == qb);
        #pragma unroll
        for (int nt = 0; nt < 16; nt++) {
            const int c0 = 8 * nt + 2 * tig;
            if (diag) {
                if (c0     > r0)     s[nt][0] = -1e30f;
                if (c0 + 1 > r0)     s[nt][1] = -1e30f;
                if (c0     > r0 + 8) s[nt][2] = -1e30f;
                if (c0 + 1 > r0 + 8) s[nt][3] = -1e30f;
            }
            mx0 = fmaxf(mx0, fmaxf(s[nt][0], s[nt][1]));
            mx1 = fmaxf(mx1, fmaxf(s[nt][2], s[nt][3]));
        }
        mx0 = fmaxf(mx0, __shfl_xor_sync(0xffffffffu, mx0, 1));
        mx0 = fmaxf(mx0, __shfl_xor_sync(0xffffffffu, mx0, 2));
        mx1 = fmaxf(mx1, __shfl_xor_sync(0xffffffffu, mx1, 1));
        mx1 = fmaxf(mx1, __shfl_xor_sync(0xffffffffu, mx1, 2));

        const float mn0 = fmaxf(m0r, mx0);
        const float mn1 = fmaxf(m1r, mx1);
        const float corr0 = __expf(m0r - mn0);
        const float corr1 = __expf(m1r - mn1);
        m0r = mn0; m1r = mn1;

        // ---- exp (rna-rounded to tf32), P -> smem, row sums ----
        float sum0 = 0.f, sum1 = 0.f;
        #pragma unroll
        for (int nt = 0; nt < 16; nt++) {
            float p0 = tf32_rna(__expf(s[nt][0] - mn0));
            float p1 = tf32_rna(__expf(s[nt][1] - mn0));
            float p2 = tf32_rna(__expf(s[nt][2] - mn1));
            float p3 = tf32_rna(__expf(s[nt][3] - mn1));
            sum0 += p0 + p1;
            sum1 += p2 + p3;
            *(float2*)&Ps[(r0)     * LDP + 8 * nt + 2 * tig] = make_float2(p0, p1);
            *(float2*)&Ps[(r0 + 8) * LDP + 8 * nt + 2 * tig] = make_float2(p2, p3);
        }
        sum0 += __shfl_xor_sync(0xffffffffu, sum0, 1);
        sum0 += __shfl_xor_sync(0xffffffffu, sum0, 2);
        sum1 += __shfl_xor_sync(0xffffffffu, sum1, 1);
        sum1 += __shfl_xor_sync(0xffffffffu, sum1, 2);
        l0 = l0 * corr0 + sum0;
        l1 = l1 * corr1 + sum1;

        // rescale O
        #pragma unroll
        for (int n = 0; n < 8; n++) {
            O[n][0] *= corr0; O[n][1] *= corr0;
            O[n][2] *= corr1; O[n][3] *= corr1;
        }
        __syncwarp();   // own-warp P rows: sts -> lds ordering

        // ---- O += P V : 16 k-steps x 8 n-tiles ----
        #pragma unroll
        for (int k2 = 0; k2 < 16; k2++) {
            uint32_t a[4];
            a[0] = *(const uint32_t*)&Ps[(r0)     * LDP + 8 * k2 + tig];
            a[1] = *(const uint32_t*)&Ps[(r0 + 8) * LDP + 8 * k2 + tig];
            a[2] = *(const uint32_t*)&Ps[(r0)     * LDP + 8 * k2 + tig + 4];
            a[3] = *(const uint32_t*)&Ps[(r0 + 8) * LDP + 8 * k2 + tig + 4];
            #pragma unroll
            for (int nt = 0; nt < 8; nt++) {
                uint32_t b0 = *(const uint32_t*)&Vs[(8 * k2 + tig)     * LDV + 8 * nt + g];
                uint32_t b1 = *(const uint32_t*)&Vs[(8 * k2 + tig + 4) * LDV + 8 * nt + g];
                mma_tf32(O[nt], a, b0, b1);
            }
        }

        buf ^= 1;
    }

    // ---- epilogue ----
    const float inv0 = 1.0f / l0;
    const float inv1 = 1.0f / l1;
    float* o0 = out + ((size_t)(b * TSEQ + q0 + wrow + g)) * HEAD;
    float* o1 = out + ((size_t)(b * TSEQ + q0 + wrow + g + 8)) * HEAD;
    #pragma unroll
    for (int nt = 0; nt < 8; nt++) {
        *(float2*)&o0[8 * nt + 2 * tig] = make_float2(O[nt][0] * inv0, O[nt][1] * inv0);
        *(float2*)&o1[8 * nt + 2 * tig] = make_float2(O[nt][2] * inv1, O[nt][3] * inv1);
    }
}

extern "C" void kernel_launch(void* const* d_in, const int* in_sizes, int n_in,
                              void* d_out, int out_size)
{
    const float* x  = (const float*)d_in[0];
    const float* Wk = (const float*)d_in[1];
    const float* Wq = (const float*)d_in[2];
    const float* Wv = (const float*)d_in[3];
    float* out = (float*)d_out;

    cudaFuncSetAttribute(proj_kernel,
                         cudaFuncAttributeMaxDynamicSharedMemorySize,
                         PROJ_SMEM_FLOATS * (int)sizeof(float));
    cudaFuncSetAttribute(attn_kernel,
                         cudaFuncAttributeMaxDynamicSharedMemorySize,
                         ATTN_SMEM_FLOATS * (int)sizeof(float));

    proj_kernel<<<dim3(BT / 128), 256, PROJ_SMEM_FLOATS * sizeof(float)>>>(x, Wk, Wq, Wv);
    attn_kernel<<<dim3(NQT, NB), 256, ATTN_SMEM_FLOATS * sizeof(float)>>>(out);
}

// round 10
// speedup vs baseline: 2.7857x; 1.0853x over previous
#include <cuda_runtime.h>
#include <cstdint>

#define TSEQ 4096
#define NB   4
#define BT   (TSEQ * NB)
#define CDIM 1024
#define HEAD 64
#define QT   128               // queries per attn CTA
#define NQT  (TSEQ / QT)       // 32 query tiles per batch
#define SPLIT_QB 16            // qb >= SPLIT_QB gets 2 CTAs (KV halves)

// Scratch (allocation-free rule: __device__ globals)
__device__ float g_Q[BT * HEAD];
__device__ float g_K[BT * HEAD];
__device__ float g_V[BT * HEAD];
// Split-KV partials: [half][b][qb-16][row][col] and per-row (m, l)
__device__ float g_Op[2 * NB * 16 * 128 * HEAD];
__device__ float g_ml[2 * NB * 16 * 128 * 2];

__device__ __forceinline__ float tf32_rna(float x) {
    uint32_t u;
    asm("cvt.rna.tf32.f32 %0, %1;" : "=r"(u) : "f"(x));
    return __uint_as_float(u);
}

// m16n8k8 tf32 mma: A row-major (4 regs), B col-major (2 regs), C fp32 (4 regs)
__device__ __forceinline__ void mma_tf32(float* c, const uint32_t* a,
                                         uint32_t b0, uint32_t b1) {
    asm volatile(
        "mma.sync.aligned.m16n8k8.row.col.f32.tf32.tf32.f32 "
        "{%0,%1,%2,%3}, {%4,%5,%6,%7}, {%8,%9}, {%0,%1,%2,%3};"
        : "+f"(c[0]), "+f"(c[1]), "+f"(c[2]), "+f"(c[3])
        : "r"(a[0]), "r"(a[1]), "r"(a[2]), "r"(a[3]), "r"(b0), "r"(b1));
}

__device__ __forceinline__ void cp16(uint32_t s, const void* g) {
    asm volatile("cp.async.cg.shared.global [%0], [%1], 16;" :: "r"(s), "l"(g));
}
#define CP_COMMIT() asm volatile("cp.async.commit_group;" ::: "memory")
#define CP_WAIT0()  asm volatile("cp.async.wait_group 0;" ::: "memory")

__device__ __forceinline__ uint32_t smem_u32(const void* p) {
    uint32_t a;
    asm("{ .reg .u64 t; cvta.to.shared.u64 t, %1; cvt.u32.u64 %0, t; }"
        : "=r"(a) : "l"(p));
    return a;
}

// ===========================================================================
// Projection via 3xTF32 mma (error-compensated; ~fp32 accuracy).
// One CTA: 128 rows x 192 cols (K|Q|V). 8 warps as 4x2; warp tile 32x96.
// ===========================================================================
#define XPITCH 36
#define WPITCH 200
#define XH_OFF 0
#define XL_OFF (128 * XPITCH)
#define WH_OFF (2 * 128 * XPITCH)
#define WL_OFF (WH_OFF + 32 * WPITCH)
#define PROJ_SMEM_FLOATS (WL_OFF + 32 * WPITCH)

__global__ __launch_bounds__(256, 1) void proj_kernel(
    const float* __restrict__ x, const float* __restrict__ Wk,
    const float* __restrict__ Wq, const float* __restrict__ Wv)
{
    extern __shared__ float psm[];
    float* xh = psm + XH_OFF;
    float* xl = psm + XL_OFF;
    float* wh = psm + WH_OFF;
    float* wl = psm + WL_OFF;

    const int tid  = threadIdx.x;
    const int w    = tid >> 5;
    const int lane = tid & 31;
    const int g    = lane >> 2;
    const int tig  = lane & 3;
    const int wr   = w >> 1;      // 0..3
    const int wc   = w & 1;       // 0..1
    const int m0   = blockIdx.x * 128;

    const float* Wm[3] = {Wk, Wq, Wv};

    float acc[2][12][4];
    #pragma unroll
    for (int mt = 0; mt < 2; mt++)
        #pragma unroll
        for (int n = 0; n < 12; n++)
            #pragma unroll
            for (int c = 0; c < 4; c++) acc[mt][n][c] = 0.f;

    for (int k0 = 0; k0 < CDIM; k0 += 32) {
        #pragma unroll
        for (int i = 0; i < 4; i++) {
            int idx = tid + i * 256;
            int r = idx >> 3, c4 = idx & 7;
            float4 v = *(const float4*)&x[(size_t)(m0 + r) * CDIM + k0 + c4 * 4];
            float h0 = tf32_rna(v.x), h1 = tf32_rna(v.y),
                  h2 = tf32_rna(v.z), h3 = tf32_rna(v.w);
            float* ph = &xh[r * XPITCH + c4 * 4];
            float* pl = &xl[r * XPITCH + c4 * 4];
            ph[0] = h0; ph[1] = h1; ph[2] = h2; ph[3] = h3;
            pl[0] = tf32_rna(v.x - h0); pl[1] = tf32_rna(v.y - h1);
            pl[2] = tf32_rna(v.z - h2); pl[3] = tf32_rna(v.w - h3);
        }
        #pragma unroll
        for (int m = 0; m < 3; m++) {
            #pragma unroll
            for (int i = 0; i < 2; i++) {
                int idx = tid + i * 256;
                int r = idx >> 4, c4 = idx & 15;
                float4 v = *(const float4*)&Wm[m][(size_t)(k0 + r) * HEAD + c4 * 4];
                float h0 = tf32_rna(v.x), h1 = tf32_rna(v.y),
                      h2 = tf32_rna(v.z), h3 = tf32_rna(v.w);
                float* ph = &wh[r * WPITCH + m * 64 + c4 * 4];
                float* pl = &wl[r * WPITCH + m * 64 + c4 * 4];
                ph[0] = h0; ph[1] = h1; ph[2] = h2; ph[3] = h3;
                pl[0] = tf32_rna(v.x - h0); pl[1] = tf32_rna(v.y - h1);
                pl[2] = tf32_rna(v.z - h2); pl[3] = tf32_rna(v.w - h3);
            }
        }
        __syncthreads();

        #pragma unroll
        for (int ks = 0; ks < 4; ks++) {
            uint32_t ah[2][4], al[2][4];
            #pragma unroll
            for (int mt = 0; mt < 2; mt++) {
                const int rb = 32 * wr + 16 * mt;
                ah[mt][0] = __float_as_uint(xh[(rb + g)     * XPITCH + 8 * ks + tig]);
                ah[mt][1] = __float_as_uint(xh[(rb + g + 8) * XPITCH + 8 * ks + tig]);
                ah[mt][2] = __float_as_uint(xh[(rb + g)     * XPITCH + 8 * ks + tig + 4]);
                ah[mt][3] = __float_as_uint(xh[(rb + g + 8) * XPITCH + 8 * ks + tig + 4]);
                al[mt][0] = __float_as_uint(xl[(rb + g)     * XPITCH + 8 * ks + tig]);
                al[mt][1] = __float_as_uint(xl[(rb + g + 8) * XPITCH + 8 * ks + tig]);
                al[mt][2] = __float_as_uint(xl[(rb + g)     * XPITCH + 8 * ks + tig + 4]);
                al[mt][3] = __float_as_uint(xl[(rb + g + 8) * XPITCH + 8 * ks + tig + 4]);
            }
            #pragma unroll
            for (int n = 0; n < 12; n++) {
                const int col = 96 * wc + 8 * n + g;
                uint32_t bh0 = __float_as_uint(wh[(8 * ks + tig)     * WPITCH + col]);
                uint32_t bh1 = __float_as_uint(wh[(8 * ks + tig + 4) * WPITCH + col]);
                uint32_t bl0 = __float_as_uint(wl[(8 * ks + tig)     * WPITCH + col]);
                uint32_t bl1 = __float_as_uint(wl[(8 * ks + tig + 4) * WPITCH + col]);
                #pragma unroll
                for (int mt = 0; mt < 2; mt++) {
                    mma_tf32(acc[mt][n], al[mt], bh0, bh1);
                    mma_tf32(acc[mt][n], ah[mt], bl0, bl1);
                    mma_tf32(acc[mt][n], ah[mt], bh0, bh1);
                }
            }
        }
        __syncthreads();
    }

    float* Om[3] = {g_K, g_Q, g_V};
    #pragma unroll
    for (int n = 0; n < 12; n++) {
        const int colg = 96 * wc + 8 * n + 2 * tig;
        float* dst = Om[colg >> 6];
        const int cin = colg & 63;
        #pragma unroll
        for (int mt = 0; mt < 2; mt++) {
            const int row = m0 + 32 * wr + 16 * mt + g;
            *(float2*)&dst[(size_t)row * HEAD + cin] =
                make_float2(tf32_rna(acc[mt][n][0]), tf32_rna(acc[mt][n][1]));
            *(float2*)&dst[(size_t)(row + 8) * HEAD + cin] =
                make_float2(tf32_rna(acc[mt][n][2]), tf32_rna(acc[mt][n][3]));
        }
    }
}

// ===========================================================================
// Flash attention, mma.sync tf32, cp.async double-buffered K/V, SPLIT-KV:
// qb < 16: one CTA, full range, writes out directly.
// qb >= 16: two CTAs (KV halves), write unnormalized partials + (m,l).
// Grid x: 0..31 = splits (heaviest first: qb = 31 - x/2), 32..47 = solos.
// ===========================================================================
#define LDK 68
#define LDV 72
#define LDP 136
#define KS_SZ (128 * LDK)
#define VS_SZ (128 * LDV)
#define KS_OFF 0
#define VS_OFF (2 * KS_SZ)
#define PS_OFF (VS_OFF + 2 * VS_SZ)
#define ATTN_SMEM_FLOATS (PS_OFF + 128 * LDP)

__global__ __launch_bounds__(256, 1) void attn_kernel(float* __restrict__ out)
{
    extern __shared__ float sm[];
    float* Ps = sm + PS_OFF;
    const uint32_t smb = smem_u32(sm);

    const int tid  = threadIdx.x;
    const int w    = tid >> 5;
    const int lane = tid & 31;
    const int g    = lane >> 2;
    const int tig  = lane & 3;
    const int wrow = w * 16;
    const int b    = blockIdx.y;
    const int xx   = blockIdx.x;

    int qb, half, jlo, jhi;
    bool split;
    if (xx < 32) {                       // split CTAs, heaviest first
        qb    = (NQT - 1) - (xx >> 1);   // 31 .. 16
        half  = xx & 1;
        split = true;
        const int mid = (qb + 1) >> 1;
        jlo = half ? mid : 0;
        jhi = half ? (qb + 1) : mid;
    } else {                             // solo CTAs
        qb    = 47 - xx;                 // 15 .. 0
        half  = 0;
        split = false;
        jlo = 0;
        jhi = qb + 1;
    }
    const int q0 = qb * QT;

    const int cprow = tid >> 4;
    const int cpc4  = tid & 15;

    const float* Kg0 = g_K + ((size_t)(b * TSEQ)) * HEAD;
    const float* Vg0 = g_V + ((size_t)(b * TSEQ)) * HEAD;

    // prefetch tile jlo into buffer 0
    {
        const float* Kg = Kg0 + (size_t)jlo * QT * HEAD;
        const float* Vg = Vg0 + (size_t)jlo * QT * HEAD;
        #pragma unroll
        for (int i = 0; i < 8; i++) {
            int r = cprow + i * 16;
            cp16(smb + (uint32_t)(KS_OFF + r * LDK + cpc4 * 4) * 4,
                 &Kg[(size_t)r * HEAD + cpc4 * 4]);
            cp16(smb + (uint32_t)(VS_OFF + r * LDV + cpc4 * 4) * 4,
                 &Vg[(size_t)r * HEAD + cpc4 * 4]);
        }
        CP_COMMIT();
    }

    // Preload Q A-frags (scaled by 0.125 — exact power of 2, stays tf32)
    uint32_t aq[8][4];
    {
        const float* Qb = g_Q + ((size_t)(b * TSEQ + q0 + wrow)) * HEAD;
        #pragma unroll
        for (int k = 0; k < 8; k++) {
            aq[k][0] = __float_as_uint(0.125f * Qb[(size_t)g * HEAD + 8 * k + tig]);
            aq[k][1] = __float_as_uint(0.125f * Qb[(size_t)(g + 8) * HEAD + 8 * k + tig]);
            aq[k][2] = __float_as_uint(0.125f * Qb[(size_t)g * HEAD + 8 * k + tig + 4]);
            aq[k][3] = __float_as_uint(0.125f * Qb[(size_t)(g + 8) * HEAD + 8 * k + tig + 4]);
        }
    }

    float O[8][4];
    #pragma unroll
    for (int n = 0; n < 8; n++)
        #pragma unroll
        for (int c = 0; c < 4; c++) O[n][c] = 0.f;
    float m0r = -1e30f, m1r = -1e30f, l0 = 0.f, l1 = 0.f;
    int buf = 0;

    #pragma unroll 1
    for (int j = jlo; j < jhi; j++) {
        CP_WAIT0();
        __syncthreads();          // tile j visible; prev compute done

        if (j + 1 < jhi) {        // prefetch next tile into other buffer
            const int nb = buf ^ 1;
            const float* Kg = Kg0 + (size_t)(j + 1) * QT * HEAD;
            const float* Vg = Vg0 + (size_t)(j + 1) * QT * HEAD;
            #pragma unroll
            for (int i = 0; i < 8; i++) {
                int r = cprow + i * 16;
                cp16(smb + (uint32_t)(KS_OFF + nb * KS_SZ + r * LDK + cpc4 * 4) * 4,
                     &Kg[(size_t)r * HEAD + cpc4 * 4]);
                cp16(smb + (uint32_t)(VS_OFF + nb * VS_SZ + r * LDV + cpc4 * 4) * 4,
                     &Vg[(size_t)r * HEAD + cpc4 * 4]);
            }
            CP_COMMIT();
        }

        const float* Ks = sm + KS_OFF + buf * KS_SZ;
        const float* Vs = sm + VS_OFF + buf * VS_SZ;

        // ---- S = (0.125 Q) K^T : 16 n-tiles x 8 k-steps ----
        float s[16][4];
        #pragma unroll
        for (int nt = 0; nt < 16; nt++)
            #pragma unroll
            for (int c = 0; c < 4; c++) s[nt][c] = 0.f;

        #pragma unroll
        for (int k = 0; k < 8; k++) {
            #pragma unroll
            for (int nt = 0; nt < 16; nt++) {
                uint32_t b0 = *(const uint32_t*)&Ks[(8 * nt + g) * LDK + 8 * k + tig];
                uint32_t b1 = *(const uint32_t*)&Ks[(8 * nt + g) * LDK + 8 * k + tig + 4];
                mma_tf32(s[nt], aq[k], b0, b1);
            }
        }

        // ---- mask (diag tile only) + row max ----
        const int r0 = wrow + g;
        float mx0 = -1e30f, mx1 = -1e30f;
        const bool diag = (j == qb);
        #pragma unroll
        for (int nt = 0; nt < 16; nt++) {
            const int c0 = 8 * nt + 2 * tig;
            if (diag) {
                if (c0     > r0)     s[nt][0] = -1e30f;
                if (c0 + 1 > r0)     s[nt][1] = -1e30f;
                if (c0     > r0 + 8) s[nt][2] = -1e30f;
                if (c0 + 1 > r0 + 8) s[nt][3] = -1e30f;
            }
            mx0 = fmaxf(mx0, fmaxf(s[nt][0], s[nt][1]));
            mx1 = fmaxf(mx1, fmaxf(s[nt][2], s[nt][3]));
        }
        mx0 = fmaxf(mx0, __shfl_xor_sync(0xffffffffu, mx0, 1));
        mx0 = fmaxf(mx0, __shfl_xor_sync(0xffffffffu, mx0, 2));
        mx1 = fmaxf(mx1, __shfl_xor_sync(0xffffffffu, mx1, 1));
        mx1 = fmaxf(mx1, __shfl_xor_sync(0xffffffffu, mx1, 2));

        const float mn0 = fmaxf(m0r, mx0);
        const float mn1 = fmaxf(m1r, mx1);
        const float corr0 = __expf(m0r - mn0);
        const float corr1 = __expf(m1r - mn1);
        m0r = mn0; m1r = mn1;

        // ---- exp (rna to tf32), P -> smem, row sums ----
        float sum0 = 0.f, sum1 = 0.f;
        #pragma unroll
        for (int nt = 0; nt < 16; nt++) {
            float p0 = tf32_rna(__expf(s[nt][0] - mn0));
            float p1 = tf32_rna(__expf(s[nt][1] - mn0));
            float p2 = tf32_rna(__expf(s[nt][2] - mn1));
            float p3 = tf32_rna(__expf(s[nt][3] - mn1));
            sum0 += p0 + p1;
            sum1 += p2 + p3;
            *(float2*)&Ps[(r0)     * LDP + 8 * nt + 2 * tig] = make_float2(p0, p1);
            *(float2*)&Ps[(r0 + 8) * LDP + 8 * nt + 2 * tig] = make_float2(p2, p3);
        }
        sum0 += __shfl_xor_sync(0xffffffffu, sum0, 1);
        sum0 += __shfl_xor_sync(0xffffffffu, sum0, 2);
        sum1 += __shfl_xor_sync(0xffffffffu, sum1, 1);
        sum1 += __shfl_xor_sync(0xffffffffu, sum1, 2);
        l0 = l0 * corr0 + sum0;
        l1 = l1 * corr1 + sum1;

        #pragma unroll
        for (int n = 0; n < 8; n++) {
            O[n][0] *= corr0; O[n][1] *= corr0;
            O[n][2] *= corr1; O[n][3] *= corr1;
        }
        __syncwarp();   // own-warp P rows: sts -> lds ordering

        // ---- O += P V : 16 k-steps x 8 n-tiles ----
        #pragma unroll
        for (int k2 = 0; k2 < 16; k2++) {
            uint32_t a[4];
            a[0] = *(const uint32_t*)&Ps[(r0)     * LDP + 8 * k2 + tig];
            a[1] = *(const uint32_t*)&Ps[(r0 + 8) * LDP + 8 * k2 + tig];
            a[2] = *(const uint32_t*)&Ps[(r0)     * LDP + 8 * k2 + tig + 4];
            a[3] = *(const uint32_t*)&Ps[(r0 + 8) * LDP + 8 * k2 + tig + 4];
            #pragma unroll
            for (int nt = 0; nt < 8; nt++) {
                uint32_t b0 = *(const uint32_t*)&Vs[(8 * k2 + tig)     * LDV + 8 * nt + g];
                uint32_t b1 = *(const uint32_t*)&Vs[(8 * k2 + tig + 4) * LDV + 8 * nt + g];
                mma_tf32(O[nt], a, b0, b1);
            }
        }

        buf ^= 1;
    }

    // ---- epilogue ----
    if (!split) {
        const float inv0 = 1.0f / l0;
        const float inv1 = 1.0f / l1;
        float* o0 = out + ((size_t)(b * TSEQ + q0 + wrow + g)) * HEAD;
        float* o1 = out + ((size_t)(b * TSEQ + q0 + wrow + g + 8)) * HEAD;
        #pragma unroll
        for (int nt = 0; nt < 8; nt++) {
            *(float2*)&o0[8 * nt + 2 * tig] = make_float2(O[nt][0] * inv0, O[nt][1] * inv0);
            *(float2*)&o1[8 * nt + 2 * tig] = make_float2(O[nt][2] * inv1, O[nt][3] * inv1);
        }
    } else {
        const size_t base = (((size_t)half * NB + b) * 16 + (qb - SPLIT_QB)) * 128;
        float* Op0 = g_Op + (base + wrow + g) * HEAD;
        float* Op1 = g_Op + (base + wrow + g + 8) * HEAD;
        #pragma unroll
        for (int nt = 0; nt < 8; nt++) {
            *(float2*)&Op0[8 * nt + 2 * tig] = make_float2(O[nt][0], O[nt][1]);
            *(float2*)&Op1[8 * nt + 2 * tig] = make_float2(O[nt][2], O[nt][3]);
        }
        if (tig == 0) {
            *(float2*)&g_ml[(base + wrow + g) * 2]     = make_float2(m0r, l0);
            *(float2*)&g_ml[(base + wrow + g + 8) * 2] = make_float2(m1r, l1);
        }
    }
}

// ===========================================================================
// Combine the two KV-half partials for qb >= 16 (exact flash merge).
// Grid (16, NB), 256 threads: thread -> (row = tid/2, 32-col chunk).
// ===========================================================================
__global__ __launch_bounds__(256, 4) void reduce_kernel(float* __restrict__ out)
{
    const int qi = blockIdx.x;           // qb = 16 + qi
    const int b  = blockIdx.y;
    const int tid = threadIdx.x;
    const int r  = tid >> 1;
    const int cb = (tid & 1) * 32;

    const size_t i0 = (((size_t)0 * NB + b) * 16 + qi) * 128 + r;
    const size_t i1 = (((size_t)1 * NB + b) * 16 + qi) * 128 + r;
    const float2 mlA = *(const float2*)&g_ml[i0 * 2];
    const float2 mlB = *(const float2*)&g_ml[i1 * 2];
    const float M  = fmaxf(mlA.x, mlB.x);
    const float eA = __expf(mlA.x - M);
    const float eB = __expf(mlB.x - M);
    const float inv = 1.0f / (mlA.y * eA + mlB.y * eB);

    const float* OA = g_Op + i0 * HEAD;
    const float* OB = g_Op + i1 * HEAD;
    float* o = out + ((size_t)(b * TSEQ + (SPLIT_QB + qi) * QT + r)) * HEAD;
    #pragma unroll
    for (int c = cb; c < cb + 32; c += 4) {
        float4 a = *(const float4*)&OA[c];
        float4 v = *(const float4*)&OB[c];
        *(float4*)&o[c] = make_float4((a.x * eA + v.x * eB) * inv,
                                      (a.y * eA + v.y * eB) * inv,
                                      (a.z * eA + v.z * eB) * inv,
                                      (a.w * eA + v.w * eB) * inv);
    }
}

extern "C" void kernel_launch(void* const* d_in, const int* in_sizes, int n_in,
                              void* d_out, int out_size)
{
    const float* x  = (const float*)d_in[0];
    const float* Wk = (const float*)d_in[1];
    const float* Wq = (const float*)d_in[2];
    const float* Wv = (const float*)d_in[3];
    float* out = (float*)d_out;

    cudaFuncSetAttribute(proj_kernel,
                         cudaFuncAttributeMaxDynamicSharedMemorySize,
                         PROJ_SMEM_FLOATS * (int)sizeof(float));
    cudaFuncSetAttribute(attn_kernel,
                         cudaFuncAttributeMaxDynamicSharedMemorySize,
                         ATTN_SMEM_FLOATS * (int)sizeof(float));

    proj_kernel<<<dim3(BT / 128), 256, PROJ_SMEM_FLOATS * sizeof(float)>>>(x, Wk, Wq, Wv);
    attn_kernel<<<dim3(48, NB), 256, ATTN_SMEM_FLOATS * sizeof(float)>>>(out);
    reduce_kernel<<<dim3(16, NB), 256>>>(out);
}

// round 11
// speedup vs baseline: 2.8075x; 1.0078x over previous
#include <cuda_runtime.h>
#include <cstdint>

#define TSEQ 4096
#define NB   4
#define BT   (TSEQ * NB)
#define CDIM 1024
#define HEAD 64
#define QT   128               // queries per attn CTA
#define NQT  (TSEQ / QT)       // 32 query tiles per batch
#define SPLIT_QB 16            // qb >= SPLIT_QB gets 2 CTAs (KV halves)

// Scratch (allocation-free rule: __device__ globals)
__device__ float g_Q[BT * HEAD];
__device__ float g_K[BT * HEAD];
__device__ float g_V[BT * HEAD];
// Split-KV partials: [half][b][qb-16][row][col] and per-row (m, l)
__device__ float g_Op[2 * NB * 16 * 128 * HEAD];
__device__ float g_ml[2 * NB * 16 * 128 * 2];

__device__ __forceinline__ float tf32_rna(float x) {
    uint32_t u;
    asm("cvt.rna.tf32.f32 %0, %1;" : "=r"(u) : "f"(x));
    return __uint_as_float(u);
}

// m16n8k8 tf32 mma: A row-major (4 regs), B col-major (2 regs), C fp32 (4 regs)
__device__ __forceinline__ void mma_tf32(float* c, const uint32_t* a,
                                         uint32_t b0, uint32_t b1) {
    asm volatile(
        "mma.sync.aligned.m16n8k8.row.col.f32.tf32.tf32.f32 "
        "{%0,%1,%2,%3}, {%4,%5,%6,%7}, {%8,%9}, {%0,%1,%2,%3};"
        : "+f"(c[0]), "+f"(c[1]), "+f"(c[2]), "+f"(c[3])
        : "r"(a[0]), "r"(a[1]), "r"(a[2]), "r"(a[3]), "r"(b0), "r"(b1));
}

__device__ __forceinline__ void cp16(uint32_t s, const void* g) {
    asm volatile("cp.async.cg.shared.global [%0], [%1], 16;" :: "r"(s), "l"(g));
}
#define CP_COMMIT() asm volatile("cp.async.commit_group;" ::: "memory")
#define CP_WAIT0()  asm volatile("cp.async.wait_group 0;" ::: "memory")

__device__ __forceinline__ uint32_t smem_u32(const void* p) {
    uint32_t a;
    asm("{ .reg .u64 t; cvta.to.shared.u64 t, %1; cvt.u32.u64 %0, t; }"
        : "=r"(a) : "l"(p));
    return a;
}

// ===========================================================================
// Projection via 3xTF32 mma (error-compensated; ~fp32 accuracy).
// One CTA: 128 rows x 192 cols (K|Q|V). 8 warps as 4x2; warp tile 32x96.
// ===========================================================================
#define XPITCH 36
#define WPITCH 200
#define XH_OFF 0
#define XL_OFF (128 * XPITCH)
#define WH_OFF (2 * 128 * XPITCH)
#define WL_OFF (WH_OFF + 32 * WPITCH)
#define PROJ_SMEM_FLOATS (WL_OFF + 32 * WPITCH)

__global__ __launch_bounds__(256, 1) void proj_kernel(
    const float* __restrict__ x, const float* __restrict__ Wk,
    const float* __restrict__ Wq, const float* __restrict__ Wv)
{
    extern __shared__ float psm[];
    float* xh = psm + XH_OFF;
    float* xl = psm + XL_OFF;
    float* wh = psm + WH_OFF;
    float* wl = psm + WL_OFF;

    const int tid  = threadIdx.x;
    const int w    = tid >> 5;
    const int lane = tid & 31;
    const int g    = lane >> 2;
    const int tig  = lane & 3;
    const int wr   = w >> 1;      // 0..3
    const int wc   = w & 1;       // 0..1
    const int m0   = blockIdx.x * 128;

    const float* Wm[3] = {Wk, Wq, Wv};

    float acc[2][12][4];
    #pragma unroll
    for (int mt = 0; mt < 2; mt++)
        #pragma unroll
        for (int n = 0; n < 12; n++)
            #pragma unroll
            for (int c = 0; c < 4; c++) acc[mt][n][c] = 0.f;

    for (int k0 = 0; k0 < CDIM; k0 += 32) {
        #pragma unroll
        for (int i = 0; i < 4; i++) {
            int idx = tid + i * 256;
            int r = idx >> 3, c4 = idx & 7;
            float4 v = *(const float4*)&x[(size_t)(m0 + r) * CDIM + k0 + c4 * 4];
            float h0 = tf32_rna(v.x), h1 = tf32_rna(v.y),
                  h2 = tf32_rna(v.z), h3 = tf32_rna(v.w);
            float* ph = &xh[r * XPITCH + c4 * 4];
            float* pl = &xl[r * XPITCH + c4 * 4];
            ph[0] = h0; ph[1] = h1; ph[2] = h2; ph[3] = h3;
            pl[0] = tf32_rna(v.x - h0); pl[1] = tf32_rna(v.y - h1);
            pl[2] = tf32_rna(v.z - h2); pl[3] = tf32_rna(v.w - h3);
        }
        #pragma unroll
        for (int m = 0; m < 3; m++) {
            #pragma unroll
            for (int i = 0; i < 2; i++) {
                int idx = tid + i * 256;
                int r = idx >> 4, c4 = idx & 15;
                float4 v = *(const float4*)&Wm[m][(size_t)(k0 + r) * HEAD + c4 * 4];
                float h0 = tf32_rna(v.x), h1 = tf32_rna(v.y),
                      h2 = tf32_rna(v.z), h3 = tf32_rna(v.w);
                float* ph = &wh[r * WPITCH + m * 64 + c4 * 4];
                float* pl = &wl[r * WPITCH + m * 64 + c4 * 4];
                ph[0] = h0; ph[1] = h1; ph[2] = h2; ph[3] = h3;
                pl[0] = tf32_rna(v.x - h0); pl[1] = tf32_rna(v.y - h1);
                pl[2] = tf32_rna(v.z - h2); pl[3] = tf32_rna(v.w - h3);
            }
        }
        __syncthreads();

        #pragma unroll
        for (int ks = 0; ks < 4; ks++) {
            uint32_t ah[2][4], al[2][4];
            #pragma unroll
            for (int mt = 0; mt < 2; mt++) {
                const int rb = 32 * wr + 16 * mt;
                ah[mt][0] = __float_as_uint(xh[(rb + g)     * XPITCH + 8 * ks + tig]);
                ah[mt][1] = __float_as_uint(xh[(rb + g + 8) * XPITCH + 8 * ks + tig]);
                ah[mt][2] = __float_as_uint(xh[(rb + g)     * XPITCH + 8 * ks + tig + 4]);
                ah[mt][3] = __float_as_uint(xh[(rb + g + 8) * XPITCH + 8 * ks + tig + 4]);
                al[mt][0] = __float_as_uint(xl[(rb + g)     * XPITCH + 8 * ks + tig]);
                al[mt][1] = __float_as_uint(xl[(rb + g + 8) * XPITCH + 8 * ks + tig]);
                al[mt][2] = __float_as_uint(xl[(rb + g)     * XPITCH + 8 * ks + tig + 4]);
                al[mt][3] = __float_as_uint(xl[(rb + g + 8) * XPITCH + 8 * ks + tig + 4]);
            }
            #pragma unroll
            for (int n = 0; n < 12; n++) {
                const int col = 96 * wc + 8 * n + g;
                uint32_t bh0 = __float_as_uint(wh[(8 * ks + tig)     * WPITCH + col]);
                uint32_t bh1 = __float_as_uint(wh[(8 * ks + tig + 4) * WPITCH + col]);
                uint32_t bl0 = __float_as_uint(wl[(8 * ks + tig)     * WPITCH + col]);
                uint32_t bl1 = __float_as_uint(wl[(8 * ks + tig + 4) * WPITCH + col]);
                #pragma unroll
                for (int mt = 0; mt < 2; mt++) {
                    mma_tf32(acc[mt][n], al[mt], bh0, bh1);
                    mma_tf32(acc[mt][n], ah[mt], bl0, bl1);
                    mma_tf32(acc[mt][n], ah[mt], bh0, bh1);
                }
            }
        }
        __syncthreads();
    }

    float* Om[3] = {g_K, g_Q, g_V};
    #pragma unroll
    for (int n = 0; n < 12; n++) {
        const int colg = 96 * wc + 8 * n + 2 * tig;
        float* dst = Om[colg >> 6];
        const int cin = colg & 63;
        #pragma unroll
        for (int mt = 0; mt < 2; mt++) {
            const int row = m0 + 32 * wr + 16 * mt + g;
            *(float2*)&dst[(size_t)row * HEAD + cin] =
                make_float2(tf32_rna(acc[mt][n][0]), tf32_rna(acc[mt][n][1]));
            *(float2*)&dst[(size_t)(row + 8) * HEAD + cin] =
                make_float2(tf32_rna(acc[mt][n][2]), tf32_rna(acc[mt][n][3]));
        }
    }
}

// ===========================================================================
// Flash attention, mma.sync tf32, cp.async double-buffered K/V, SPLIT-KV:
// qb < 16: one CTA, full range, writes out directly.
// qb >= 16: two CTAs (KV halves), write unnormalized partials + (m,l).
// Grid x: 0..31 = splits (heaviest first: qb = 31 - x/2), 32..47 = solos.
// ===========================================================================
#define LDK 68
#define LDV 72
#define LDP 136
#define KS_SZ (128 * LDK)
#define VS_SZ (128 * LDV)
#define KS_OFF 0
#define VS_OFF (2 * KS_SZ)
#define PS_OFF (VS_OFF + 2 * VS_SZ)
#define ATTN_SMEM_FLOATS (PS_OFF + 128 * LDP)

__global__ __launch_bounds__(256, 1) void attn_kernel(float* __restrict__ out)
{
    extern __shared__ float sm[];
    float* Ps = sm + PS_OFF;
    const uint32_t smb = smem_u32(sm);

    const int tid  = threadIdx.x;
    const int w    = tid >> 5;
    const int lane = tid & 31;
    const int g    = lane >> 2;
    const int tig  = lane & 3;
    const int wrow = w * 16;
    const int b    = blockIdx.y;
    const int xx   = blockIdx.x;

    int qb, half, jlo, jhi;
    bool split;
    if (xx < 32) {                       // split CTAs, heaviest first
        qb    = (NQT - 1) - (xx >> 1);   // 31 .. 16
        half  = xx & 1;
        split = true;
        const int mid = (qb + 1) >> 1;
        jlo = half ? mid : 0;
        jhi = half ? (qb + 1) : mid;
    } else {                             // solo CTAs
        qb    = 47 - xx;                 // 15 .. 0
        half  = 0;
        split = false;
        jlo = 0;
        jhi = qb + 1;
    }
    const int q0 = qb * QT;

    const int cprow = tid >> 4;
    const int cpc4  = tid & 15;

    const float* Kg0 = g_K + ((size_t)(b * TSEQ)) * HEAD;
    const float* Vg0 = g_V + ((size_t)(b * TSEQ)) * HEAD;

    // prefetch tile jlo into buffer 0
    {
        const float* Kg = Kg0 + (size_t)jlo * QT * HEAD;
        const float* Vg = Vg0 + (size_t)jlo * QT * HEAD;
        #pragma unroll
        for (int i = 0; i < 8; i++) {
            int r = cprow + i * 16;
            cp16(smb + (uint32_t)(KS_OFF + r * LDK + cpc4 * 4) * 4,
                 &Kg[(size_t)r * HEAD + cpc4 * 4]);
            cp16(smb + (uint32_t)(VS_OFF + r * LDV + cpc4 * 4) * 4,
                 &Vg[(size_t)r * HEAD + cpc4 * 4]);
        }
        CP_COMMIT();
    }

    // Preload Q A-frags (scaled by 0.125 — exact power of 2, stays tf32)
    uint32_t aq[8][4];
    {
        const float* Qb = g_Q + ((size_t)(b * TSEQ + q0 + wrow)) * HEAD;
        #pragma unroll
        for (int k = 0; k < 8; k++) {
            aq[k][0] = __float_as_uint(0.125f * Qb[(size_t)g * HEAD + 8 * k + tig]);
            aq[k][1] = __float_as_uint(0.125f * Qb[(size_t)(g + 8) * HEAD + 8 * k + tig]);
            aq[k][2] = __float_as_uint(0.125f * Qb[(size_t)g * HEAD + 8 * k + tig + 4]);
            aq[k][3] = __float_as_uint(0.125f * Qb[(size_t)(g + 8) * HEAD + 8 * k + tig + 4]);
        }
    }

    float O[8][4];
    #pragma unroll
    for (int n = 0; n < 8; n++)
        #pragma unroll
        for (int c = 0; c < 4; c++) O[n][c] = 0.f;
    float m0r = -1e30f, m1r = -1e30f, l0 = 0.f, l1 = 0.f;
    int buf = 0;

    #pragma unroll 1
    for (int j = jlo; j < jhi; j++) {
        CP_WAIT0();
        __syncthreads();          // tile j visible; prev compute done

        if (j + 1 < jhi) {        // prefetch next tile into other buffer
            const int nb = buf ^ 1;
            const float* Kg = Kg0 + (size_t)(j + 1) * QT * HEAD;
            const float* Vg = Vg0 + (size_t)(j + 1) * QT * HEAD;
            #pragma unroll
            for (int i = 0; i < 8; i++) {
                int r = cprow + i * 16;
                cp16(smb + (uint32_t)(KS_OFF + nb * KS_SZ + r * LDK + cpc4 * 4) * 4,
                     &Kg[(size_t)r * HEAD + cpc4 * 4]);
                cp16(smb + (uint32_t)(VS_OFF + nb * VS_SZ + r * LDV + cpc4 * 4) * 4,
                     &Vg[(size_t)r * HEAD + cpc4 * 4]);
            }
            CP_COMMIT();
        }

        const float* Ks = sm + KS_OFF + buf * KS_SZ;
        const float* Vs = sm + VS_OFF + buf * VS_SZ;

        // ---- S = (0.125 Q) K^T : 16 n-tiles x 8 k-steps ----
        float s[16][4];
        #pragma unroll
        for (int nt = 0; nt < 16; nt++)
            #pragma unroll
            for (int c = 0; c < 4; c++) s[nt][c] = 0.f;

        #pragma unroll
        for (int k = 0; k < 8; k++) {
            #pragma unroll
            for (int nt = 0; nt < 16; nt++) {
                uint32_t b0 = *(const uint32_t*)&Ks[(8 * nt + g) * LDK + 8 * k + tig];
                uint32_t b1 = *(const uint32_t*)&Ks[(8 * nt + g) * LDK + 8 * k + tig + 4];
                mma_tf32(s[nt], aq[k], b0, b1);
            }
        }

        // ---- mask (diag tile only) + row max ----
        const int r0 = wrow + g;
        float mx0 = -1e30f, mx1 = -1e30f;
        const bool diag = (j == qb);
        #pragma unroll
        for (int nt = 0; nt < 16; nt++) {
            const int c0 = 8 * nt + 2 * tig;
            if (diag) {
                if (c0     > r0)     s[nt][0] = -1e30f;
                if (c0 + 1 > r0)     s[nt][1] = -1e30f;
                if (c0     > r0 + 8) s[nt][2] = -1e30f;
                if (c0 + 1 > r0 + 8) s[nt][3] = -1e30f;
            }
            mx0 = fmaxf(mx0, fmaxf(s[nt][0], s[nt][1]));
            mx1 = fmaxf(mx1, fmaxf(s[nt][2], s[nt][3]));
        }
        mx0 = fmaxf(mx0, __shfl_xor_sync(0xffffffffu, mx0, 1));
        mx0 = fmaxf(mx0, __shfl_xor_sync(0xffffffffu, mx0, 2));
        mx1 = fmaxf(mx1, __shfl_xor_sync(0xffffffffu, mx1, 1));
        mx1 = fmaxf(mx1, __shfl_xor_sync(0xffffffffu, mx1, 2));

        const float mn0 = fmaxf(m0r, mx0);
        const float mn1 = fmaxf(m1r, mx1);
        const float corr0 = __expf(m0r - mn0);
        const float corr1 = __expf(m1r - mn1);
        m0r = mn0; m1r = mn1;

        // ---- exp (rna to tf32), P -> smem, row sums ----
        float sum0 = 0.f, sum1 = 0.f;
        #pragma unroll
        for (int nt = 0; nt < 16; nt++) {
            float p0 = tf32_rna(__expf(s[nt][0] - mn0));
            float p1 = tf32_rna(__expf(s[nt][1] - mn0));
            float p2 = tf32_rna(__expf(s[nt][2] - mn1));
            float p3 = tf32_rna(__expf(s[nt][3] - mn1));
            sum0 += p0 + p1;
            sum1 += p2 + p3;
            *(float2*)&Ps[(r0)     * LDP + 8 * nt + 2 * tig] = make_float2(p0, p1);
            *(float2*)&Ps[(r0 + 8) * LDP + 8 * nt + 2 * tig] = make_float2(p2, p3);
        }
        sum0 += __shfl_xor_sync(0xffffffffu, sum0, 1);
        sum0 += __shfl_xor_sync(0xffffffffu, sum0, 2);
        sum1 += __shfl_xor_sync(0xffffffffu, sum1, 1);
        sum1 += __shfl_xor_sync(0xffffffffu, sum1, 2);
        l0 = l0 * corr0 + sum0;
        l1 = l1 * corr1 + sum1;

        #pragma unroll
        for (int n = 0; n < 8; n++) {
            O[n][0] *= corr0; O[n][1] *= corr0;
            O[n][2] *= corr1; O[n][3] *= corr1;
        }
        __syncwarp();   // own-warp P rows: sts -> lds ordering

        // ---- O += P V : 16 k-steps x 8 n-tiles ----
        #pragma unroll
        for (int k2 = 0; k2 < 16; k2++) {
            uint32_t a[4];
            a[0] = *(const uint32_t*)&Ps[(r0)     * LDP + 8 * k2 + tig];
            a[1] = *(const uint32_t*)&Ps[(r0 + 8) * LDP + 8 * k2 + tig];
            a[2] = *(const uint32_t*)&Ps[(r0)     * LDP + 8 * k2 + tig + 4];
            a[3] = *(const uint32_t*)&Ps[(r0 + 8) * LDP + 8 * k2 + tig + 4];
            #pragma unroll
            for (int nt = 0; nt < 8; nt++) {
                uint32_t b0 = *(const uint32_t*)&Vs[(8 * k2 + tig)     * LDV + 8 * nt + g];
                uint32_t b1 = *(const uint32_t*)&Vs[(8 * k2 + tig + 4) * LDV + 8 * nt + g];
                mma_tf32(O[nt], a, b0, b1);
            }
        }

        buf ^= 1;
    }

    // ---- epilogue ----
    if (!split) {
        const float inv0 = 1.0f / l0;
        const float inv1 = 1.0f / l1;
        float* o0 = out + ((size_t)(b * TSEQ + q0 + wrow + g)) * HEAD;
        float* o1 = out + ((size_t)(b * TSEQ + q0 + wrow + g + 8)) * HEAD;
        #pragma unroll
        for (int nt = 0; nt < 8; nt++) {
            *(float2*)&o0[8 * nt + 2 * tig] = make_float2(O[nt][0] * inv0, O[nt][1] * inv0);
            *(float2*)&o1[8 * nt + 2 * tig] = make_float2(O[nt][2] * inv1, O[nt][3] * inv1);
        }
    } else {
        const size_t base = (((size_t)half * NB + b) * 16 + (qb - SPLIT_QB)) * 128;
        float* Op0 = g_Op + (base + wrow + g) * HEAD;
        float* Op1 = g_Op + (base + wrow + g + 8) * HEAD;
        #pragma unroll
        for (int nt = 0; nt < 8; nt++) {
            *(float2*)&Op0[8 * nt + 2 * tig] = make_float2(O[nt][0], O[nt][1]);
            *(float2*)&Op1[8 * nt + 2 * tig] = make_float2(O[nt][2], O[nt][3]);
        }
        if (tig == 0) {
            *(float2*)&g_ml[(base + wrow + g) * 2]     = make_float2(m0r, l0);
            *(float2*)&g_ml[(base + wrow + g + 8) * 2] = make_float2(m1r, l1);
        }
    }
}

// ===========================================================================
// Combine the two KV-half partials for qb >= 16 (exact flash merge).
// Grid (16, NB), 256 threads: thread -> (row = tid/2, 32-col chunk).
// ===========================================================================
__global__ __launch_bounds__(256, 4) void reduce_kernel(float* __restrict__ out)
{
    const int qi = blockIdx.x;           // qb = 16 + qi
    const int b  = blockIdx.y;
    const int tid = threadIdx.x;
    const int r  = tid >> 1;
    const int cb = (tid & 1) * 32;

    const size_t i0 = (((size_t)0 * NB + b) * 16 + qi) * 128 + r;
    const size_t i1 = (((size_t)1 * NB + b) * 16 + qi) * 128 + r;
    const float2 mlA = *(const float2*)&g_ml[i0 * 2];
    const float2 mlB = *(const float2*)&g_ml[i1 * 2];
    const float M  = fmaxf(mlA.x, mlB.x);
    const float eA = __expf(mlA.x - M);
    const float eB = __expf(mlB.x - M);
    const float inv = 1.0f / (mlA.y * eA + mlB.y * eB);

    const float* OA = g_Op + i0 * HEAD;
    const float* OB = g_Op + i1 * HEAD;
    float* o = out + ((size_t)(b * TSEQ + (SPLIT_QB + qi) * QT + r)) * HEAD;
    #pragma unroll
    for (int c = cb; c < cb + 32; c += 4) {
        float4 a = *(const float4*)&OA[c];
        float4 v = *(const float4*)&OB[c];
        *(float4*)&o[c] = make_float4((a.x * eA + v.x * eB) * inv,
                                      (a.y * eA + v.y * eB) * inv,
                                      (a.z * eA + v.z * eB) * inv,
                                      (a.w * eA + v.w * eB) * inv);
    }
}

extern "C" void kernel_launch(void* const* d_in, const int* in_sizes, int n_in,
                              void* d_out, int out_size)
{
    const float* x  = (const float*)d_in[0];
    const float* Wk = (const float*)d_in[1];
    const float* Wq = (const float*)d_in[2];
    const float* Wv = (const float*)d_in[3];
    float* out = (float*)d_out;

    cudaFuncSetAttribute(proj_kernel,
                         cudaFuncAttributeMaxDynamicSharedMemorySize,
                         PROJ_SMEM_FLOATS * (int)sizeof(float));
    cudaFuncSetAttribute(attn_kernel,
                         cudaFuncAttributeMaxDynamicSharedMemorySize,
                         ATTN_SMEM_FLOATS * (int)sizeof(float));

    proj_kernel<<<dim3(BT / 128), 256, PROJ_SMEM_FLOATS * sizeof(float)>>>(x, Wk, Wq, Wv);
    attn_kernel<<<dim3(48, NB), 256, ATTN_SMEM_FLOATS * sizeof(float)>>>(out);
    reduce_kernel<<<dim3(16, NB), 256>>>(out);
}

// round 12
// speedup vs baseline: 3.9671x; 1.4130x over previous
#include <cuda_runtime.h>
#include <cstdint>

#define TSEQ 4096
#define NB   4
#define BT   (TSEQ * NB)
#define CDIM 1024
#define HEAD 64
#define QT   128               // queries per attn CTA
#define NQT  (TSEQ / QT)       // 32 query tiles per batch
#define SPLIT_QB 16            // qb >= SPLIT_QB gets 2 CTAs (KV halves)

// Scratch (allocation-free rule: __device__ globals)
__device__ float g_Q[BT * HEAD];
__device__ float g_K[BT * HEAD];
__device__ float g_V[BT * HEAD];
// Split-KV partials: [half][b][qb-16][row][col] and per-row (m, l)
__device__ float g_Op[2 * NB * 16 * 128 * HEAD];
__device__ float g_ml[2 * NB * 16 * 128 * 2];

__device__ __forceinline__ float tf32_rna(float x) {
    uint32_t u;
    asm("cvt.rna.tf32.f32 %0, %1;" : "=r"(u) : "f"(x));
    return __uint_as_float(u);
}
__device__ __forceinline__ uint32_t tf32_rna_u(float x) {
    uint32_t u;
    asm("cvt.rna.tf32.f32 %0, %1;" : "=r"(u) : "f"(x));
    return u;
}

// m16n8k8 tf32 mma: A row-major (4 regs), B col-major (2 regs), C fp32 (4 regs)
__device__ __forceinline__ void mma_tf32(float* c, const uint32_t* a,
                                         uint32_t b0, uint32_t b1) {
    asm volatile(
        "mma.sync.aligned.m16n8k8.row.col.f32.tf32.tf32.f32 "
        "{%0,%1,%2,%3}, {%4,%5,%6,%7}, {%8,%9}, {%0,%1,%2,%3};"
        : "+f"(c[0]), "+f"(c[1]), "+f"(c[2]), "+f"(c[3])
        : "r"(a[0]), "r"(a[1]), "r"(a[2]), "r"(a[3]), "r"(b0), "r"(b1));
}

__device__ __forceinline__ void cp16(uint32_t s, const void* g) {
    asm volatile("cp.async.cg.shared.global [%0], [%1], 16;" :: "r"(s), "l"(g));
}
#define CP_COMMIT() asm volatile("cp.async.commit_group;" ::: "memory")
#define CP_WAIT0()  asm volatile("cp.async.wait_group 0;" ::: "memory")

__device__ __forceinline__ uint32_t smem_u32(const void* p) {
    uint32_t a;
    asm("{ .reg .u64 t; cvta.to.shared.u64 t, %1; cvt.u32.u64 %0, t; }"
        : "=r"(a) : "l"(p));
    return a;
}

// ===========================================================================
// Projection, single-pass tf32 mma + cp.async double buffering.
// One CTA: 128 rows x 192 cols (K|Q|V). 8 warps as 4x2; warp tile 32x96.
// Raw f32 tiles in smem; frags rna-rounded in registers before the mma
// (unbiased, vs the HW's truncate-to-tf32).
// ===========================================================================
#define XPITCH 36
#define WPITCH 200
#define XT_SZ (128 * XPITCH)
#define WT_SZ (32 * WPITCH)
#define X_OFF 0
#define W_OFF (2 * XT_SZ)
#define PROJ_SMEM_FLOATS (W_OFF + 2 * WT_SZ)

__global__ __launch_bounds__(256, 1) void proj_kernel(
    const float* __restrict__ x, const float* __restrict__ Wk,
    const float* __restrict__ Wq, const float* __restrict__ Wv)
{
    extern __shared__ float psm[];
    const uint32_t smb = smem_u32(psm);

    const int tid  = threadIdx.x;
    const int w    = tid >> 5;
    const int lane = tid & 31;
    const int g    = lane >> 2;
    const int tig  = lane & 3;
    const int wr   = w >> 1;      // 0..3
    const int wc   = w & 1;       // 0..1
    const int m0   = blockIdx.x * 128;

    const float* Wm[3] = {Wk, Wq, Wv};

    // cp.async slots
    const int xr  = tid >> 1;            // x: 1024 slots, 4/thread (i*2 stride on c4)
    const int xc4 = (tid & 1) << 2;      // c4 base 0 or 4, +2 per i... use idx form below
    (void)xr; (void)xc4;

    // prefetch chunk 0 into buffer 0
    {
        #pragma unroll
        for (int i = 0; i < 4; i++) {
            int idx = tid + i * 256;             // 1024 float4 slots
            int r = idx >> 3, c4 = idx & 7;
            cp16(smb + (uint32_t)(X_OFF + r * XPITCH + c4 * 4) * 4,
                 &x[(size_t)(m0 + r) * CDIM + 0 + c4 * 4]);
        }
        #pragma unroll
        for (int m = 0; m < 3; m++) {
            #pragma unroll
            for (int i = 0; i < 2; i++) {
                int idx = tid + i * 256;         // 512 float4 slots
                int r = idx >> 4, c4 = idx & 15;
                cp16(smb + (uint32_t)(W_OFF + r * WPITCH + m * 64 + c4 * 4) * 4,
                     &Wm[m][(size_t)(0 + r) * HEAD + c4 * 4]);
            }
        }
        CP_COMMIT();
    }

    float acc[2][12][4];
    #pragma unroll
    for (int mt = 0; mt < 2; mt++)
        #pragma unroll
        for (int n = 0; n < 12; n++)
            #pragma unroll
            for (int c = 0; c < 4; c++) acc[mt][n][c] = 0.f;

    int buf = 0;
    #pragma unroll 1
    for (int k0 = 0; k0 < CDIM; k0 += 32) {
        CP_WAIT0();
        __syncthreads();

        if (k0 + 32 < CDIM) {            // prefetch next chunk into other buffer
            const int nb = buf ^ 1;
            const int kn = k0 + 32;
            #pragma unroll
            for (int i = 0; i < 4; i++) {
                int idx = tid + i * 256;
                int r = idx >> 3, c4 = idx & 7;
                cp16(smb + (uint32_t)(X_OFF + nb * XT_SZ + r * XPITCH + c4 * 4) * 4,
                     &x[(size_t)(m0 + r) * CDIM + kn + c4 * 4]);
            }
            #pragma unroll
            for (int m = 0; m < 3; m++) {
                #pragma unroll
                for (int i = 0; i < 2; i++) {
                    int idx = tid + i * 256;
                    int r = idx >> 4, c4 = idx & 15;
                    cp16(smb + (uint32_t)(W_OFF + nb * WT_SZ + r * WPITCH + m * 64 + c4 * 4) * 4,
                         &Wm[m][(size_t)(kn + r) * HEAD + c4 * 4]);
                }
            }
            CP_COMMIT();
        }

        const float* xs = psm + X_OFF + buf * XT_SZ;
        const float* ws = psm + W_OFF + buf * WT_SZ;

        #pragma unroll
        for (int ks = 0; ks < 4; ks++) {
            uint32_t a[2][4];
            #pragma unroll
            for (int mt = 0; mt < 2; mt++) {
                const int rb = 32 * wr + 16 * mt;
                a[mt][0] = tf32_rna_u(xs[(rb + g)     * XPITCH + 8 * ks + tig]);
                a[mt][1] = tf32_rna_u(xs[(rb + g + 8) * XPITCH + 8 * ks + tig]);
                a[mt][2] = tf32_rna_u(xs[(rb + g)     * XPITCH + 8 * ks + tig + 4]);
                a[mt][3] = tf32_rna_u(xs[(rb + g + 8) * XPITCH + 8 * ks + tig + 4]);
            }
            #pragma unroll
            for (int n = 0; n < 12; n++) {
                const int col = 96 * wc + 8 * n + g;
                uint32_t b0 = tf32_rna_u(ws[(8 * ks + tig)     * WPITCH + col]);
                uint32_t b1 = tf32_rna_u(ws[(8 * ks + tig + 4) * WPITCH + col]);
                mma_tf32(acc[0][n], a[0], b0, b1);
                mma_tf32(acc[1][n], a[1], b0, b1);
            }
        }
        __syncthreads();
        buf ^= 1;
    }

    // epilogue: rna-round once, store to g_K/g_Q/g_V
    float* Om[3] = {g_K, g_Q, g_V};
    #pragma unroll
    for (int n = 0; n < 12; n++) {
        const int colg = 96 * wc + 8 * n + 2 * tig;
        float* dst = Om[colg >> 6];
        const int cin = colg & 63;
        #pragma unroll
        for (int mt = 0; mt < 2; mt++) {
            const int row = m0 + 32 * wr + 16 * mt + g;
            *(float2*)&dst[(size_t)row * HEAD + cin] =
                make_float2(tf32_rna(acc[mt][n][0]), tf32_rna(acc[mt][n][1]));
            *(float2*)&dst[(size_t)(row + 8) * HEAD + cin] =
                make_float2(tf32_rna(acc[mt][n][2]), tf32_rna(acc[mt][n][3]));
        }
    }
}

// ===========================================================================
// Flash attention, mma.sync tf32, cp.async double-buffered K/V, SPLIT-KV:
// qb < 16: one CTA, full range, writes out directly.
// qb >= 16: two CTAs (KV halves), write unnormalized partials + (m,l).
// Grid x: 0..31 = splits (heaviest first: qb = 31 - x/2), 32..47 = solos.
// (unchanged from the 266us round)
// ===========================================================================
#define LDK 68
#define LDV 72
#define LDP 136
#define KS_SZ (128 * LDK)
#define VS_SZ (128 * LDV)
#define KS_OFF 0
#define VS_OFF (2 * KS_SZ)
#define PS_OFF (VS_OFF + 2 * VS_SZ)
#define ATTN_SMEM_FLOATS (PS_OFF + 128 * LDP)

__global__ __launch_bounds__(256, 1) void attn_kernel(float* __restrict__ out)
{
    extern __shared__ float sm[];
    float* Ps = sm + PS_OFF;
    const uint32_t smb = smem_u32(sm);

    const int tid  = threadIdx.x;
    const int w    = tid >> 5;
    const int lane = tid & 31;
    const int g    = lane >> 2;
    const int tig  = lane & 3;
    const int wrow = w * 16;
    const int b    = blockIdx.y;
    const int xx   = blockIdx.x;

    int qb, half, jlo, jhi;
    bool split;
    if (xx < 32) {                       // split CTAs, heaviest first
        qb    = (NQT - 1) - (xx >> 1);   // 31 .. 16
        half  = xx & 1;
        split = true;
        const int mid = (qb + 1) >> 1;
        jlo = half ? mid : 0;
        jhi = half ? (qb + 1) : mid;
    } else {                             // solo CTAs
        qb    = 47 - xx;                 // 15 .. 0
        half  = 0;
        split = false;
        jlo = 0;
        jhi = qb + 1;
    }
    const int q0 = qb * QT;

    const int cprow = tid >> 4;
    const int cpc4  = tid & 15;

    const float* Kg0 = g_K + ((size_t)(b * TSEQ)) * HEAD;
    const float* Vg0 = g_V + ((size_t)(b * TSEQ)) * HEAD;

    // prefetch tile jlo into buffer 0
    {
        const float* Kg = Kg0 + (size_t)jlo * QT * HEAD;
        const float* Vg = Vg0 + (size_t)jlo * QT * HEAD;
        #pragma unroll
        for (int i = 0; i < 8; i++) {
            int r = cprow + i * 16;
            cp16(smb + (uint32_t)(KS_OFF + r * LDK + cpc4 * 4) * 4,
                 &Kg[(size_t)r * HEAD + cpc4 * 4]);
            cp16(smb + (uint32_t)(VS_OFF + r * LDV + cpc4 * 4) * 4,
                 &Vg[(size_t)r * HEAD + cpc4 * 4]);
        }
        CP_COMMIT();
    }

    // Preload Q A-frags (scaled by 0.125 — exact power of 2, stays tf32)
    uint32_t aq[8][4];
    {
        const float* Qb = g_Q + ((size_t)(b * TSEQ + q0 + wrow)) * HEAD;
        #pragma unroll
        for (int k = 0; k < 8; k++) {
            aq[k][0] = __float_as_uint(0.125f * Qb[(size_t)g * HEAD + 8 * k + tig]);
            aq[k][1] = __float_as_uint(0.125f * Qb[(size_t)(g + 8) * HEAD + 8 * k + tig]);
            aq[k][2] = __float_as_uint(0.125f * Qb[(size_t)g * HEAD + 8 * k + tig + 4]);
            aq[k][3] = __float_as_uint(0.125f * Qb[(size_t)(g + 8) * HEAD + 8 * k + tig + 4]);
        }
    }

    float O[8][4];
    #pragma unroll
    for (int n = 0; n < 8; n++)
        #pragma unroll
        for (int c = 0; c < 4; c++) O[n][c] = 0.f;
    float m0r = -1e30f, m1r = -1e30f, l0 = 0.f, l1 = 0.f;
    int buf = 0;

    #pragma unroll 1
    for (int j = jlo; j < jhi; j++) {
        CP_WAIT0();
        __syncthreads();          // tile j visible; prev compute done

        if (j + 1 < jhi) {        // prefetch next tile into other buffer
            const int nb = buf ^ 1;
            const float* Kg = Kg0 + (size_t)(j + 1) * QT * HEAD;
            const float* Vg = Vg0 + (size_t)(j + 1) * QT * HEAD;
            #pragma unroll
            for (int i = 0; i < 8; i++) {
                int r = cprow + i * 16;
                cp16(smb + (uint32_t)(KS_OFF + nb * KS_SZ + r * LDK + cpc4 * 4) * 4,
                     &Kg[(size_t)r * HEAD + cpc4 * 4]);
                cp16(smb + (uint32_t)(VS_OFF + nb * VS_SZ + r * LDV + cpc4 * 4) * 4,
                     &Vg[(size_t)r * HEAD + cpc4 * 4]);
            }
            CP_COMMIT();
        }

        const float* Ks = sm + KS_OFF + buf * KS_SZ;
        const float* Vs = sm + VS_OFF + buf * VS_SZ;

        // ---- S = (0.125 Q) K^T : 16 n-tiles x 8 k-steps ----
        float s[16][4];
        #pragma unroll
        for (int nt = 0; nt < 16; nt++)
            #pragma unroll
            for (int c = 0; c < 4; c++) s[nt][c] = 0.f;

        #pragma unroll
        for (int k = 0; k < 8; k++) {
            #pragma unroll
            for (int nt = 0; nt < 16; nt++) {
                uint32_t b0 = *(const uint32_t*)&Ks[(8 * nt + g) * LDK + 8 * k + tig];
                uint32_t b1 = *(const uint32_t*)&Ks[(8 * nt + g) * LDK + 8 * k + tig + 4];
                mma_tf32(s[nt], aq[k], b0, b1);
            }
        }

        // ---- mask (diag tile only) + row max ----
        const int r0 = wrow + g;
        float mx0 = -1e30f, mx1 = -1e30f;
        const bool diag = (j == qb);
        #pragma unroll
        for (int nt = 0; nt < 16; nt++) {
            const int c0 = 8 * nt + 2 * tig;
            if (diag) {
                if (c0     > r0)     s[nt][0] = -1e30f;
                if (c0 + 1 > r0)     s[nt][1] = -1e30f;
                if (c0     > r0 + 8) s[nt][2] = -1e30f;
                if (c0 + 1 > r0 + 8) s[nt][3] = -1e30f;
            }
            mx0 = fmaxf(mx0, fmaxf(s[nt][0], s[nt][1]));
            mx1 = fmaxf(mx1, fmaxf(s[nt][2], s[nt][3]));
        }
        mx0 = fmaxf(mx0, __shfl_xor_sync(0xffffffffu, mx0, 1));
        mx0 = fmaxf(mx0, __shfl_xor_sync(0xffffffffu, mx0, 2));
        mx1 = fmaxf(mx1, __shfl_xor_sync(0xffffffffu, mx1, 1));
        mx1 = fmaxf(mx1, __shfl_xor_sync(0xffffffffu, mx1, 2));

        const float mn0 = fmaxf(m0r, mx0);
        const float mn1 = fmaxf(m1r, mx1);
        const float corr0 = __expf(m0r - mn0);
        const float corr1 = __expf(m1r - mn1);
        m0r = mn0; m1r = mn1;

        // ---- exp (rna to tf32), P -> smem, row sums ----
        float sum0 = 0.f, sum1 = 0.f;
        #pragma unroll
        for (int nt = 0; nt < 16; nt++) {
            float p0 = tf32_rna(__expf(s[nt][0] - mn0));
            float p1 = tf32_rna(__expf(s[nt][1] - mn0));
            float p2 = tf32_rna(__expf(s[nt][2] - mn1));
            float p3 = tf32_rna(__expf(s[nt][3] - mn1));
            sum0 += p0 + p1;
            sum1 += p2 + p3;
            *(float2*)&Ps[(r0)     * LDP + 8 * nt + 2 * tig] = make_float2(p0, p1);
            *(float2*)&Ps[(r0 + 8) * LDP + 8 * nt + 2 * tig] = make_float2(p2, p3);
        }
        sum0 += __shfl_xor_sync(0xffffffffu, sum0, 1);
        sum0 += __shfl_xor_sync(0xffffffffu, sum0, 2);
        sum1 += __shfl_xor_sync(0xffffffffu, sum1, 1);
        sum1 += __shfl_xor_sync(0xffffffffu, sum1, 2);
        l0 = l0 * corr0 + sum0;
        l1 = l1 * corr1 + sum1;

        #pragma unroll
        for (int n = 0; n < 8; n++) {
            O[n][0] *= corr0; O[n][1] *= corr0;
            O[n][2] *= corr1; O[n][3] *= corr1;
        }
        __syncwarp();   // own-warp P rows: sts -> lds ordering

        // ---- O += P V : 16 k-steps x 8 n-tiles ----
        #pragma unroll
        for (int k2 = 0; k2 < 16; k2++) {
            uint32_t a[4];
            a[0] = *(const uint32_t*)&Ps[(r0)     * LDP + 8 * k2 + tig];
            a[1] = *(const uint32_t*)&Ps[(r0 + 8) * LDP + 8 * k2 + tig];
            a[2] = *(const uint32_t*)&Ps[(r0)     * LDP + 8 * k2 + tig + 4];
            a[3] = *(const uint32_t*)&Ps[(r0 + 8) * LDP + 8 * k2 + tig + 4];
            #pragma unroll
            for (int nt = 0; nt < 8; nt++) {
                uint32_t b0 = *(const uint32_t*)&Vs[(8 * k2 + tig)     * LDV + 8 * nt + g];
                uint32_t b1 = *(const uint32_t*)&Vs[(8 * k2 + tig + 4) * LDV + 8 * nt + g];
                mma_tf32(O[nt], a, b0, b1);
            }
        }

        buf ^= 1;
    }

    // ---- epilogue ----
    if (!split) {
        const float inv0 = 1.0f / l0;
        const float inv1 = 1.0f / l1;
        float* o0 = out + ((size_t)(b * TSEQ + q0 + wrow + g)) * HEAD;
        float* o1 = out + ((size_t)(b * TSEQ + q0 + wrow + g + 8)) * HEAD;
        #pragma unroll
        for (int nt = 0; nt < 8; nt++) {
            *(float2*)&o0[8 * nt + 2 * tig] = make_float2(O[nt][0] * inv0, O[nt][1] * inv0);
            *(float2*)&o1[8 * nt + 2 * tig] = make_float2(O[nt][2] * inv1, O[nt][3] * inv1);
        }
    } else {
        const size_t base = (((size_t)half * NB + b) * 16 + (qb - SPLIT_QB)) * 128;
        float* Op0 = g_Op + (base + wrow + g) * HEAD;
        float* Op1 = g_Op + (base + wrow + g + 8) * HEAD;
        #pragma unroll
        for (int nt = 0; nt < 8; nt++) {
            *(float2*)&Op0[8 * nt + 2 * tig] = make_float2(O[nt][0], O[nt][1]);
            *(float2*)&Op1[8 * nt + 2 * tig] = make_float2(O[nt][2], O[nt][3]);
        }
        if (tig == 0) {
            *(float2*)&g_ml[(base + wrow + g) * 2]     = make_float2(m0r, l0);
            *(float2*)&g_ml[(base + wrow + g + 8) * 2] = make_float2(m1r, l1);
        }
    }
}

// ===========================================================================
// Combine the two KV-half partials for qb >= 16 (exact flash merge).
// ===========================================================================
__global__ __launch_bounds__(256, 4) void reduce_kernel(float* __restrict__ out)
{
    const int qi = blockIdx.x;           // qb = 16 + qi
    const int b  = blockIdx.y;
    const int tid = threadIdx.x;
    const int r  = tid >> 1;
    const int cb = (tid & 1) * 32;

    const size_t i0 = (((size_t)0 * NB + b) * 16 + qi) * 128 + r;
    const size_t i1 = (((size_t)1 * NB + b) * 16 + qi) * 128 + r;
    const float2 mlA = *(const float2*)&g_ml[i0 * 2];
    const float2 mlB = *(const float2*)&g_ml[i1 * 2];
    const float M  = fmaxf(mlA.x, mlB.x);
    const float eA = __expf(mlA.x - M);
    const float eB = __expf(mlB.x - M);
    const float inv = 1.0f / (mlA.y * eA + mlB.y * eB);

    const float* OA = g_Op + i0 * HEAD;
    const float* OB = g_Op + i1 * HEAD;
    float* o = out + ((size_t)(b * TSEQ + (SPLIT_QB + qi) * QT + r)) * HEAD;
    #pragma unroll
    for (int c = cb; c < cb + 32; c += 4) {
        float4 a = *(const float4*)&OA[c];
        float4 v = *(const float4*)&OB[c];
        *(float4*)&o[c] = make_float4((a.x * eA + v.x * eB) * inv,
                                      (a.y * eA + v.y * eB) * inv,
                                      (a.z * eA + v.z * eB) * inv,
                                      (a.w * eA + v.w * eB) * inv);
    }
}

extern "C" void kernel_launch(void* const* d_in, const int* in_sizes, int n_in,
                              void* d_out, int out_size)
{
    const float* x  = (const float*)d_in[0];
    const float* Wk = (const float*)d_in[1];
    const float* Wq = (const float*)d_in[2];
    const float* Wv = (const float*)d_in[3];
    float* out = (float*)d_out;

    cudaFuncSetAttribute(proj_kernel,
                         cudaFuncAttributeMaxDynamicSharedMemorySize,
                         PROJ_SMEM_FLOATS * (int)sizeof(float));
    cudaFuncSetAttribute(attn_kernel,
                         cudaFuncAttributeMaxDynamicSharedMemorySize,
                         ATTN_SMEM_FLOATS * (int)sizeof(float));

    proj_kernel<<<dim3(BT / 128), 256, PROJ_SMEM_FLOATS * sizeof(float)>>>(x, Wk, Wq, Wv);
    attn_kernel<<<dim3(48, NB), 256, ATTN_SMEM_FLOATS * sizeof(float)>>>(out);
    reduce_kernel<<<dim3(16, NB), 256>>>(out);
}

// round 13
// speedup vs baseline: 4.1943x; 1.0573x over previous
#include <cuda_runtime.h>
#include <cstdint>

#define TSEQ 4096
#define NB   4
#define BT   (TSEQ * NB)
#define CDIM 1024
#define HEAD 64
#define QT   128               // queries per attn CTA
#define NQT  (TSEQ / QT)       // 32 query tiles per batch
#define KT   64                // kv rows per tile

// Scratch (allocation-free rule: __device__ globals)
__device__ float g_Q[BT * HEAD];
__device__ float g_K[BT * HEAD];
__device__ float g_V[BT * HEAD];
// Split-KV partials: slot [ch][b][qb][row] ; ch < 4
__device__ float g_Op[4 * NB * NQT * 128 * HEAD];
__device__ float g_ml[4 * NB * NQT * 128 * 2];

__device__ __forceinline__ float tf32_rna(float x) {
    uint32_t u;
    asm("cvt.rna.tf32.f32 %0, %1;" : "=r"(u) : "f"(x));
    return __uint_as_float(u);
}
__device__ __forceinline__ uint32_t tf32_rna_u(float x) {
    uint32_t u;
    asm("cvt.rna.tf32.f32 %0, %1;" : "=r"(u) : "f"(x));
    return u;
}

// m16n8k8 tf32 mma: A row-major (4 regs), B col-major (2 regs), C fp32 (4 regs)
__device__ __forceinline__ void mma_tf32(float* c, const uint32_t* a,
                                         uint32_t b0, uint32_t b1) {
    asm volatile(
        "mma.sync.aligned.m16n8k8.row.col.f32.tf32.tf32.f32 "
        "{%0,%1,%2,%3}, {%4,%5,%6,%7}, {%8,%9}, {%0,%1,%2,%3};"
        : "+f"(c[0]), "+f"(c[1]), "+f"(c[2]), "+f"(c[3])
        : "r"(a[0]), "r"(a[1]), "r"(a[2]), "r"(a[3]), "r"(b0), "r"(b1));
}

__device__ __forceinline__ void cp16(uint32_t s, const void* g) {
    asm volatile("cp.async.cg.shared.global [%0], [%1], 16;" :: "r"(s), "l"(g));
}
#define CP_COMMIT() asm volatile("cp.async.commit_group;" ::: "memory")
#define CP_WAIT0()  asm volatile("cp.async.wait_group 0;" ::: "memory")

__device__ __forceinline__ uint32_t smem_u32(const void* p) {
    uint32_t a;
    asm("{ .reg .u64 t; cvta.to.shared.u64 t, %1; cvt.u32.u64 %0, t; }"
        : "=r"(a) : "l"(p));
    return a;
}

// ===========================================================================
// Projection, single-pass tf32 mma + cp.async double buffering, 2 CTAs/SM.
// One CTA: 64 rows x 192 cols (K|Q|V). 8 warps as 2x4; warp tile 32x48.
// ===========================================================================
#define XPITCH 36
#define WPITCH 200
#define XT_SZ (64 * XPITCH)
#define WT_SZ (32 * WPITCH)
#define X_OFF 0
#define W_OFF (2 * XT_SZ)
#define PROJ_SMEM_FLOATS (W_OFF + 2 * WT_SZ)

__global__ __launch_bounds__(256, 2) void proj_kernel(
    const float* __restrict__ x, const float* __restrict__ Wk,
    const float* __restrict__ Wq, const float* __restrict__ Wv)
{
    extern __shared__ float psm[];
    const uint32_t smb = smem_u32(psm);

    const int tid  = threadIdx.x;
    const int w    = tid >> 5;
    const int lane = tid & 31;
    const int g    = lane >> 2;
    const int tig  = lane & 3;
    const int wr   = w >> 2;      // 0..1
    const int wc   = w & 3;       // 0..3
    const int m0   = blockIdx.x * 64;

    const float* Wm[3] = {Wk, Wq, Wv};

    // prefetch chunk 0 into buffer 0
    {
        #pragma unroll
        for (int i = 0; i < 2; i++) {
            int idx = tid + i * 256;             // 512 float4 slots
            int r = idx >> 3, c4 = idx & 7;
            cp16(smb + (uint32_t)(X_OFF + r * XPITCH + c4 * 4) * 4,
                 &x[(size_t)(m0 + r) * CDIM + 0 + c4 * 4]);
        }
        #pragma unroll
        for (int m = 0; m < 3; m++) {
            #pragma unroll
            for (int i = 0; i < 2; i++) {
                int idx = tid + i * 256;         // 512 float4 slots
                int r = idx >> 4, c4 = idx & 15;
                cp16(smb + (uint32_t)(W_OFF + r * WPITCH + m * 64 + c4 * 4) * 4,
                     &Wm[m][(size_t)(0 + r) * HEAD + c4 * 4]);
            }
        }
        CP_COMMIT();
    }

    float acc[2][6][4];
    #pragma unroll
    for (int mt = 0; mt < 2; mt++)
        #pragma unroll
        for (int n = 0; n < 6; n++)
            #pragma unroll
            for (int c = 0; c < 4; c++) acc[mt][n][c] = 0.f;

    int buf = 0;
    #pragma unroll 1
    for (int k0 = 0; k0 < CDIM; k0 += 32) {
        CP_WAIT0();
        __syncthreads();

        if (k0 + 32 < CDIM) {            // prefetch next chunk into other buffer
            const int nb = buf ^ 1;
            const int kn = k0 + 32;
            #pragma unroll
            for (int i = 0; i < 2; i++) {
                int idx = tid + i * 256;
                int r = idx >> 3, c4 = idx & 7;
                cp16(smb + (uint32_t)(X_OFF + nb * XT_SZ + r * XPITCH + c4 * 4) * 4,
                     &x[(size_t)(m0 + r) * CDIM + kn + c4 * 4]);
            }
            #pragma unroll
            for (int m = 0; m < 3; m++) {
                #pragma unroll
                for (int i = 0; i < 2; i++) {
                    int idx = tid + i * 256;
                    int r = idx >> 4, c4 = idx & 15;
                    cp16(smb + (uint32_t)(W_OFF + nb * WT_SZ + r * WPITCH + m * 64 + c4 * 4) * 4,
                         &Wm[m][(size_t)(kn + r) * HEAD + c4 * 4]);
                }
            }
            CP_COMMIT();
        }

        const float* xs = psm + X_OFF + buf * XT_SZ;
        const float* ws = psm + W_OFF + buf * WT_SZ;

        #pragma unroll
        for (int ks = 0; ks < 4; ks++) {
            uint32_t a[2][4];
            #pragma unroll
            for (int mt = 0; mt < 2; mt++) {
                const int rb = 32 * wr + 16 * mt;
                a[mt][0] = tf32_rna_u(xs[(rb + g)     * XPITCH + 8 * ks + tig]);
                a[mt][1] = tf32_rna_u(xs[(rb + g + 8) * XPITCH + 8 * ks + tig]);
                a[mt][2] = tf32_rna_u(xs[(rb + g)     * XPITCH + 8 * ks + tig + 4]);
                a[mt][3] = tf32_rna_u(xs[(rb + g + 8) * XPITCH + 8 * ks + tig + 4]);
            }
            #pragma unroll
            for (int n = 0; n < 6; n++) {
                const int col = 48 * wc + 8 * n + g;
                uint32_t b0 = tf32_rna_u(ws[(8 * ks + tig)     * WPITCH + col]);
                uint32_t b1 = tf32_rna_u(ws[(8 * ks + tig + 4) * WPITCH + col]);
                mma_tf32(acc[0][n], a[0], b0, b1);
                mma_tf32(acc[1][n], a[1], b0, b1);
            }
        }
        __syncthreads();
        buf ^= 1;
    }

    // epilogue: rna-round once, store to g_K/g_Q/g_V
    float* Om[3] = {g_K, g_Q, g_V};
    #pragma unroll
    for (int n = 0; n < 6; n++) {
        const int colg = 48 * wc + 8 * n + 2 * tig;
        float* dst = Om[colg >> 6];
        const int cin = colg & 63;
        #pragma unroll
        for (int mt = 0; mt < 2; mt++) {
            const int row = m0 + 32 * wr + 16 * mt + g;
            *(float2*)&dst[(size_t)row * HEAD + cin] =
                make_float2(tf32_rna(acc[mt][n][0]), tf32_rna(acc[mt][n][1]));
            *(float2*)&dst[(size_t)(row + 8) * HEAD + cin] =
                make_float2(tf32_rna(acc[mt][n][2]), tf32_rna(acc[mt][n][3]));
        }
    }
}

// ===========================================================================
// Flash attention, mma.sync tf32, cp.async double-buffered K/V, 64-row KV
// tiles, 2 CTAs/SM. Generalized split-KV: (b,qb) has nch = qb/8+1 chunks of
// near-equal tile counts; every CTA writes unnormalized partials (O,m,l);
// reduce_kernel combines + normalizes. Grid x = 80 chunk slots, heavy first.
// ===========================================================================
#define LDK 68
#define LDV 72
#define LDP 72
#define KS_SZ (KT * LDK)
#define VS_SZ (KT * LDV)
#define KS_OFF 0
#define VS_OFF (2 * KS_SZ)
#define PS_OFF (VS_OFF + 2 * VS_SZ)
#define ATTN_SMEM_FLOATS (PS_OFF + 128 * LDP)

__global__ __launch_bounds__(256, 2) void attn_kernel()
{
    extern __shared__ float sm[];
    float* Ps = sm + PS_OFF;
    const uint32_t smb = smem_u32(sm);

    const int tid  = threadIdx.x;
    const int w    = tid >> 5;
    const int lane = tid & 31;
    const int g    = lane >> 2;
    const int tig  = lane & 3;
    const int wrow = w * 16;
    const int b    = blockIdx.y;
    const int xx   = blockIdx.x;

    // chunk slot -> (qb, ch); heavy qb first
    int qb, ch;
    if (xx < 32)      { qb = 24 + (xx >> 2); ch = xx & 3; }
    else if (xx < 56) { int t = xx - 32; qb = 16 + t / 3; ch = t % 3; }
    else if (xx < 72) { int t = xx - 56; qb = 8 + (t >> 1); ch = t & 1; }
    else              { qb = xx - 72; ch = 0; }
    const int T    = 2 * qb + 2;           // 64-row tiles in causal range
    const int nch  = (qb >> 3) + 1;
    const int cbase = T / nch, crem = T % nch;
    const int jlo  = ch * cbase + (ch < crem ? ch : crem);
    const int jhi  = jlo + cbase + (ch < crem ? 1 : 0);
    const int q0   = qb * QT;

    const int cprow = tid >> 4;            // 0..15, +i*16
    const int cpc4  = tid & 15;

    const float* Kg0 = g_K + ((size_t)(b * TSEQ)) * HEAD;
    const float* Vg0 = g_V + ((size_t)(b * TSEQ)) * HEAD;

    // prefetch tile jlo into buffer 0 (64 rows: 1024 float4 slots, 4/thread)
    {
        const float* Kg = Kg0 + (size_t)jlo * KT * HEAD;
        const float* Vg = Vg0 + (size_t)jlo * KT * HEAD;
        #pragma unroll
        for (int i = 0; i < 4; i++) {
            int idx = tid + i * 256;
            int r = idx >> 4, c4 = idx & 15;
            cp16(smb + (uint32_t)(KS_OFF + r * LDK + c4 * 4) * 4,
                 &Kg[(size_t)r * HEAD + c4 * 4]);
            cp16(smb + (uint32_t)(VS_OFF + r * LDV + c4 * 4) * 4,
                 &Vg[(size_t)r * HEAD + c4 * 4]);
        }
        (void)cprow; (void)cpc4;
        CP_COMMIT();
    }

    // Preload Q A-frags (scaled by 0.125 — exact power of 2, stays tf32)
    uint32_t aq[8][4];
    {
        const float* Qb = g_Q + ((size_t)(b * TSEQ + q0 + wrow)) * HEAD;
        #pragma unroll
        for (int k = 0; k < 8; k++) {
            aq[k][0] = __float_as_uint(0.125f * Qb[(size_t)g * HEAD + 8 * k + tig]);
            aq[k][1] = __float_as_uint(0.125f * Qb[(size_t)(g + 8) * HEAD + 8 * k + tig]);
            aq[k][2] = __float_as_uint(0.125f * Qb[(size_t)g * HEAD + 8 * k + tig + 4]);
            aq[k][3] = __float_as_uint(0.125f * Qb[(size_t)(g + 8) * HEAD + 8 * k + tig + 4]);
        }
    }

    float O[8][4];
    #pragma unroll
    for (int n = 0; n < 8; n++)
        #pragma unroll
        for (int c = 0; c < 4; c++) O[n][c] = 0.f;
    float m0r = -1e30f, m1r = -1e30f, l0 = 0.f, l1 = 0.f;
    int buf = 0;

    #pragma unroll 1
    for (int j = jlo; j < jhi; j++) {
        CP_WAIT0();
        __syncthreads();

        if (j + 1 < jhi) {
            const int nb = buf ^ 1;
            const float* Kg = Kg0 + (size_t)(j + 1) * KT * HEAD;
            const float* Vg = Vg0 + (size_t)(j + 1) * KT * HEAD;
            #pragma unroll
            for (int i = 0; i < 4; i++) {
                int idx = tid + i * 256;
                int r = idx >> 4, c4 = idx & 15;
                cp16(smb + (uint32_t)(KS_OFF + nb * KS_SZ + r * LDK + c4 * 4) * 4,
                     &Kg[(size_t)r * HEAD + c4 * 4]);
                cp16(smb + (uint32_t)(VS_OFF + nb * VS_SZ + r * LDV + c4 * 4) * 4,
                     &Vg[(size_t)r * HEAD + c4 * 4]);
            }
            CP_COMMIT();
        }

        const float* Ks = sm + KS_OFF + buf * KS_SZ;
        const float* Vs = sm + VS_OFF + buf * VS_SZ;

        // ---- S = (0.125 Q) K^T : 8 n-tiles x 8 k-steps ----
        float s[8][4];
        #pragma unroll
        for (int nt = 0; nt < 8; nt++)
            #pragma unroll
            for (int c = 0; c < 4; c++) s[nt][c] = 0.f;

        #pragma unroll
        for (int k = 0; k < 8; k++) {
            #pragma unroll
            for (int nt = 0; nt < 8; nt++) {
                uint32_t b0 = *(const uint32_t*)&Ks[(8 * nt + g) * LDK + 8 * k + tig];
                uint32_t b1 = *(const uint32_t*)&Ks[(8 * nt + g) * LDK + 8 * k + tig + 4];
                mma_tf32(s[nt], aq[k], b0, b1);
            }
        }

        // ---- mask (tiles overlapping diagonal) + row max ----
        const int r0 = wrow + g;
        const int qg0 = q0 + r0, qg1 = qg0 + 8;
        const int kv0 = j * KT;
        float mx0 = -1e30f, mx1 = -1e30f;
        const bool msk = (j >= 2 * qb);
        #pragma unroll
        for (int nt = 0; nt < 8; nt++) {
            const int c0 = kv0 + 8 * nt + 2 * tig;
            if (msk) {
                if (c0     > qg0) s[nt][0] = -1e30f;
                if (c0 + 1 > qg0) s[nt][1] = -1e30f;
                if (c0     > qg1) s[nt][2] = -1e30f;
                if (c0 + 1 > qg1) s[nt][3] = -1e30f;
            }
            mx0 = fmaxf(mx0, fmaxf(s[nt][0], s[nt][1]));
            mx1 = fmaxf(mx1, fmaxf(s[nt][2], s[nt][3]));
        }
        mx0 = fmaxf(mx0, __shfl_xor_sync(0xffffffffu, mx0, 1));
        mx0 = fmaxf(mx0, __shfl_xor_sync(0xffffffffu, mx0, 2));
        mx1 = fmaxf(mx1, __shfl_xor_sync(0xffffffffu, mx1, 1));
        mx1 = fmaxf(mx1, __shfl_xor_sync(0xffffffffu, mx1, 2));

        const float mn0 = fmaxf(m0r, mx0);
        const float mn1 = fmaxf(m1r, mx1);
        const float corr0 = __expf(m0r - mn0);
        const float corr1 = __expf(m1r - mn1);
        m0r = mn0; m1r = mn1;

        // ---- exp (rna to tf32), P -> smem, row sums ----
        float sum0 = 0.f, sum1 = 0.f;
        #pragma unroll
        for (int nt = 0; nt < 8; nt++) {
            float p0 = tf32_rna(__expf(s[nt][0] - mn0));
            float p1 = tf32_rna(__expf(s[nt][1] - mn0));
            float p2 = tf32_rna(__expf(s[nt][2] - mn1));
            float p3 = tf32_rna(__expf(s[nt][3] - mn1));
            sum0 += p0 + p1;
            sum1 += p2 + p3;
            *(float2*)&Ps[(r0)     * LDP + 8 * nt + 2 * tig] = make_float2(p0, p1);
            *(float2*)&Ps[(r0 + 8) * LDP + 8 * nt + 2 * tig] = make_float2(p2, p3);
        }
        sum0 += __shfl_xor_sync(0xffffffffu, sum0, 1);
        sum0 += __shfl_xor_sync(0xffffffffu, sum0, 2);
        sum1 += __shfl_xor_sync(0xffffffffu, sum1, 1);
        sum1 += __shfl_xor_sync(0xffffffffu, sum1, 2);
        l0 = l0 * corr0 + sum0;
        l1 = l1 * corr1 + sum1;

        #pragma unroll
        for (int n = 0; n < 8; n++) {
            O[n][0] *= corr0; O[n][1] *= corr0;
            O[n][2] *= corr1; O[n][3] *= corr1;
        }
        __syncwarp();   // own-warp P rows: sts -> lds ordering

        // ---- O += P V : 8 k-steps x 8 n-tiles ----
        #pragma unroll
        for (int k2 = 0; k2 < 8; k2++) {
            uint32_t a[4];
            a[0] = *(const uint32_t*)&Ps[(r0)     * LDP + 8 * k2 + tig];
            a[1] = *(const uint32_t*)&Ps[(r0 + 8) * LDP + 8 * k2 + tig];
            a[2] = *(const uint32_t*)&Ps[(r0)     * LDP + 8 * k2 + tig + 4];
            a[3] = *(const uint32_t*)&Ps[(r0 + 8) * LDP + 8 * k2 + tig + 4];
            #pragma unroll
            for (int nt = 0; nt < 8; nt++) {
                uint32_t b0 = *(const uint32_t*)&Vs[(8 * k2 + tig)     * LDV + 8 * nt + g];
                uint32_t b1 = *(const uint32_t*)&Vs[(8 * k2 + tig + 4) * LDV + 8 * nt + g];
                mma_tf32(O[nt], a, b0, b1);
            }
        }

        buf ^= 1;
    }

    // ---- epilogue: unnormalized partials + (m,l) ----
    const size_t pbase = (((size_t)ch * NB + b) * NQT + qb) * 128;
    float* Op0 = g_Op + (pbase + wrow + g) * HEAD;
    float* Op1 = g_Op + (pbase + wrow + g + 8) * HEAD;
    #pragma unroll
    for (int nt = 0; nt < 8; nt++) {
        *(float2*)&Op0[8 * nt + 2 * tig] = make_float2(O[nt][0], O[nt][1]);
        *(float2*)&Op1[8 * nt + 2 * tig] = make_float2(O[nt][2], O[nt][3]);
    }
    if (tig == 0) {
        *(float2*)&g_ml[(pbase + wrow + g) * 2]     = make_float2(m0r, l0);
        *(float2*)&g_ml[(pbase + wrow + g + 8) * 2] = make_float2(m1r, l1);
    }
}

// ===========================================================================
// Combine nch partials per (b,qb) (exact flash merge) + normalize.
// Grid (NQT, NB), 256 threads: thread -> (row = tid/2, 32-col chunk).
// ===========================================================================
__global__ __launch_bounds__(256, 4) void reduce_kernel(float* __restrict__ out)
{
    const int qb = blockIdx.x;
    const int b  = blockIdx.y;
    const int tid = threadIdx.x;
    const int r  = tid >> 1;
    const int cb = (tid & 1) * 32;
    const int nch = (qb >> 3) + 1;

    float mv[4], lv[4];
    float M = -1e30f;
    for (int i = 0; i < nch; i++) {
        const size_t ib = (((size_t)i * NB + b) * NQT + qb) * 128 + r;
        float2 ml = *(const float2*)&g_ml[ib * 2];
        mv[i] = ml.x; lv[i] = ml.y;
        M = fmaxf(M, ml.x);
    }
    float L = 0.f, ef[4];
    for (int i = 0; i < nch; i++) {
        ef[i] = __expf(mv[i] - M);
        L += lv[i] * ef[i];
    }
    const float inv = 1.0f / L;

    float* o = out + ((size_t)(b * TSEQ + qb * QT + r)) * HEAD;
    #pragma unroll
    for (int c = cb; c < cb + 32; c += 4) {
        float4 acc = make_float4(0.f, 0.f, 0.f, 0.f);
        for (int i = 0; i < nch; i++) {
            const size_t ib = (((size_t)i * NB + b) * NQT + qb) * 128 + r;
            float4 v = *(const float4*)&g_Op[ib * HEAD + c];
            acc.x += v.x * ef[i]; acc.y += v.y * ef[i];
            acc.z += v.z * ef[i]; acc.w += v.w * ef[i];
        }
        *(float4*)&o[c] = make_float4(acc.x * inv, acc.y * inv,
                                      acc.z * inv, acc.w * inv);
    }
}

extern "C" void kernel_launch(void* const* d_in, const int* in_sizes, int n_in,
                              void* d_out, int out_size)
{
    const float* x  = (const float*)d_in[0];
    const float* Wk = (const float*)d_in[1];
    const float* Wq = (const float*)d_in[2];
    const float* Wv = (const float*)d_in[3];
    float* out = (float*)d_out;

    cudaFuncSetAttribute(proj_kernel,
                         cudaFuncAttributeMaxDynamicSharedMemorySize,
                         PROJ_SMEM_FLOATS * (int)sizeof(float));
    cudaFuncSetAttribute(attn_kernel,
                         cudaFuncAttributeMaxDynamicSharedMemorySize,
                         ATTN_SMEM_FLOATS * (int)sizeof(float));

    proj_kernel<<<dim3(BT / 64), 256, PROJ_SMEM_FLOATS * sizeof(float)>>>(x, Wk, Wq, Wv);
    attn_kernel<<<dim3(80, NB), 256, ATTN_SMEM_FLOATS * sizeof(float)>>>();
    reduce_kernel<<<dim3(NQT, NB), 256>>>(out);
}